// round 2
// baseline (speedup 1.0000x reference)
#include <cuda_runtime.h>
#include <math.h>
#include <math_constants.h>

// ============================================================================
// StressNNEval: F,C -> strain invariants -> 5-layer MLP (erf GELU) -> cauchy
//
// Pipeline:
//   prep_weights : fold constant latent (emb[traj] @ W1[25:153]) into bias b1',
//                  build zero-padded W1p [32,256]
//   prep_part    : per particle: eigenvalues of F^T F (closed form, double),
//                  Newton polar iteration for R = U V^T, strain[16] + C -> X0[B,32]
//   gemm x4      : fp32 tiled SGEMM 128x128x16, fused bias + exact-erf GELU
//   final        : warp-per-particle last layer (256->9) + symmetrize + R@x@F^T
// ============================================================================

#define MAXB 262144
#define HID  256

// -------- device scratch (no allocations allowed) ---------------------------
__device__ __align__(128) float g_X0[(size_t)MAXB * 32];
__device__ __align__(128) float g_actA[(size_t)MAXB * HID];
__device__ __align__(128) float g_actB[(size_t)MAXB * HID];
__device__ __align__(128) float g_R[(size_t)MAXB * 9];
__device__ __align__(128) float g_W1p[32 * HID];
__device__ __align__(128) float g_b1p[HID];

// ---------------------------------------------------------------------------
// Fold latent into bias; pad W1 (rows 0..24 used, 25..31 zero)
// ---------------------------------------------------------------------------
__global__ void prep_weights_kernel(const float* __restrict__ emb,
                                    const int* __restrict__ traj,
                                    const float* __restrict__ W1,
                                    const float* __restrict__ b1) {
    int j = threadIdx.x;                 // 0..255
    int t = traj[0];
    const float* e = emb + (size_t)t * 128;
    float s = b1[j];
#pragma unroll 4
    for (int k = 0; k < 128; ++k)
        s += e[k] * W1[(size_t)(25 + k) * HID + j];
    g_b1p[j] = s;
#pragma unroll
    for (int r = 0; r < 32; ++r)
        g_W1p[r * HID + j] = (r < 25) ? W1[(size_t)r * HID + j] : 0.0f;
}

// ---------------------------------------------------------------------------
// Per-particle: strain invariants + polar rotation R
// ---------------------------------------------------------------------------
__global__ void prep_part_kernel(const float* __restrict__ F,
                                 const float* __restrict__ C,
                                 int B) {
    int p = blockIdx.x * blockDim.x + threadIdx.x;
    if (p >= B) return;

    double Fm[3][3];
#pragma unroll
    for (int i = 0; i < 3; ++i)
#pragma unroll
        for (int j = 0; j < 3; ++j)
            Fm[i][j] = (double)F[(size_t)p * 9 + i * 3 + j];

    // G = F^T F (symmetric)
    double G[3][3];
#pragma unroll
    for (int i = 0; i < 3; ++i)
#pragma unroll
        for (int j = 0; j < 3; ++j)
            G[i][j] = Fm[0][i] * Fm[0][j] + Fm[1][i] * Fm[1][j] + Fm[2][i] * Fm[2][j];

    // eigenvalues of G (trigonometric closed form), sorted descending
    double q  = (G[0][0] + G[1][1] + G[2][2]) / 3.0;
    double p1 = G[0][1] * G[0][1] + G[0][2] * G[0][2] + G[1][2] * G[1][2];
    double p2 = (G[0][0] - q) * (G[0][0] - q) + (G[1][1] - q) * (G[1][1] - q) +
                (G[2][2] - q) * (G[2][2] - q) + 2.0 * p1;
    double e1, e2, e3;
    double pp = sqrt(p2 / 6.0);
    if (pp < 1e-30) {
        e1 = e2 = e3 = q;
    } else {
        double b00 = (G[0][0] - q) / pp, b11 = (G[1][1] - q) / pp, b22 = (G[2][2] - q) / pp;
        double b01 = G[0][1] / pp, b02 = G[0][2] / pp, b12 = G[1][2] / pp;
        double detB = b00 * (b11 * b22 - b12 * b12) - b01 * (b01 * b22 - b12 * b02) +
                      b02 * (b01 * b12 - b11 * b02);
        double r = detB * 0.5;
        r = fmin(1.0, fmax(-1.0, r));
        double phi = acos(r) / 3.0;
        e1 = q + 2.0 * pp * cos(phi);
        e3 = q + 2.0 * pp * cos(phi + 2.0 * CUDART_PI / 3.0);
        e2 = 3.0 * q - e1 - e3;
    }
    double s1 = sqrt(fmax(e1, 0.0));
    double s2 = sqrt(fmax(e2, 0.0));
    double s3 = sqrt(fmax(e3, 0.0));

    // det(F)
    double detF = Fm[0][0] * (Fm[1][1] * Fm[2][2] - Fm[1][2] * Fm[2][1]) -
                  Fm[0][1] * (Fm[1][0] * Fm[2][2] - Fm[1][2] * Fm[2][0]) +
                  Fm[0][2] * (Fm[1][0] * Fm[2][1] - Fm[1][1] * Fm[2][0]);

    // polar rotation R via Newton: X <- 0.5*(X + X^{-T}); X^{-T} = cof(X)/det(X)
    double X[3][3];
#pragma unroll
    for (int i = 0; i < 3; ++i)
#pragma unroll
        for (int j = 0; j < 3; ++j) X[i][j] = Fm[i][j];
#pragma unroll
    for (int it = 0; it < 7; ++it) {
        double c00 = X[1][1] * X[2][2] - X[1][2] * X[2][1];
        double c01 = X[1][2] * X[2][0] - X[1][0] * X[2][2];
        double c02 = X[1][0] * X[2][1] - X[1][1] * X[2][0];
        double c10 = X[0][2] * X[2][1] - X[0][1] * X[2][2];
        double c11 = X[0][0] * X[2][2] - X[0][2] * X[2][0];
        double c12 = X[0][1] * X[2][0] - X[0][0] * X[2][1];
        double c20 = X[0][1] * X[1][2] - X[0][2] * X[1][1];
        double c21 = X[0][2] * X[1][0] - X[0][0] * X[1][2];
        double c22 = X[0][0] * X[1][1] - X[0][1] * X[1][0];
        double d   = X[0][0] * c00 + X[0][1] * c01 + X[0][2] * c02;
        double id  = 0.5 / d;
        X[0][0] = 0.5 * X[0][0] + id * c00;
        X[0][1] = 0.5 * X[0][1] + id * c01;
        X[0][2] = 0.5 * X[0][2] + id * c02;
        X[1][0] = 0.5 * X[1][0] + id * c10;
        X[1][1] = 0.5 * X[1][1] + id * c11;
        X[1][2] = 0.5 * X[1][2] + id * c12;
        X[2][0] = 0.5 * X[2][0] + id * c20;
        X[2][1] = 0.5 * X[2][1] + id * c21;
        X[2][2] = 0.5 * X[2][2] + id * c22;
    }
#pragma unroll
    for (int i = 0; i < 3; ++i)
#pragma unroll
        for (int j = 0; j < 3; ++j)
            g_R[(size_t)p * 9 + i * 3 + j] = (float)X[i][j];

    // features row: [sig-1 (3), FtF-I (9), det-1, log(det)-1, f00-1, log(f00)-1, C (9), pad (7)]
    float* x0 = g_X0 + (size_t)p * 32;
    x0[0] = (float)(s1 - 1.0);
    x0[1] = (float)(s2 - 1.0);
    x0[2] = (float)(s3 - 1.0);
#pragma unroll
    for (int i = 0; i < 3; ++i)
#pragma unroll
        for (int j = 0; j < 3; ++j)
            x0[3 + i * 3 + j] = (float)(G[i][j] - ((i == j) ? 1.0 : 0.0));
    x0[12] = (float)(detF - 1.0);
    x0[13] = (float)(log(detF) - 1.0);
    double f00 = fmax((double)F[(size_t)p * 9], 1e-6);
    x0[14] = (float)(f00 - 1.0);
    x0[15] = (float)(log(f00) - 1.0);
#pragma unroll
    for (int k = 0; k < 9; ++k) x0[16 + k] = C[(size_t)p * 9 + k];
#pragma unroll
    for (int k = 25; k < 32; ++k) x0[k] = 0.0f;
}

// ---------------------------------------------------------------------------
// fp32 SGEMM: Y[M,256] = act(A[M,K] @ W[K,256] + bias), BM=BN=128, BK=16, 8x8/thr
// ---------------------------------------------------------------------------
#define BM 128
#define BN 128
#define BKK 16
#define TM 8
#define TN 8

template <int K, bool GELU>
__global__ __launch_bounds__(256, 2)
void gemm_bias_act_kernel(const float* __restrict__ A, const float* __restrict__ W,
                          const float* __restrict__ bias, float* __restrict__ Y) {
    __shared__ float As[BKK][BM + 4];
    __shared__ float Bs[BKK][BN];

    const int m0  = blockIdx.y * BM;
    const int n0  = blockIdx.x * BN;
    const int tid = threadIdx.x;
    const int tx  = tid & 15;   // 0..15  -> col group
    const int ty  = tid >> 4;   // 0..15  -> row group

    float acc[TM][TN];
#pragma unroll
    for (int i = 0; i < TM; ++i)
#pragma unroll
        for (int j = 0; j < TN; ++j) acc[i][j] = 0.0f;

    for (int kk = 0; kk < K; kk += BKK) {
        // A tile: 128x16 floats = 512 float4, 2 per thread, stored transposed
#pragma unroll
        for (int l = 0; l < 2; ++l) {
            int idx = tid + l * 256;            // 0..511
            int row = idx >> 2;                 // 0..127
            int c4  = (idx & 3) << 2;           // 0,4,8,12
            float4 v = *reinterpret_cast<const float4*>(
                &A[(size_t)(m0 + row) * K + kk + c4]);
            As[c4 + 0][row] = v.x;
            As[c4 + 1][row] = v.y;
            As[c4 + 2][row] = v.z;
            As[c4 + 3][row] = v.w;
        }
        // W tile: 16x128 floats = 512 float4
#pragma unroll
        for (int l = 0; l < 2; ++l) {
            int idx  = tid + l * 256;
            int krow = idx >> 5;                // 0..15
            int c4   = (idx & 31) << 2;         // 0..124
            *reinterpret_cast<float4*>(&Bs[krow][c4]) =
                *reinterpret_cast<const float4*>(&W[(size_t)(kk + krow) * HID + n0 + c4]);
        }
        __syncthreads();

#pragma unroll
        for (int k = 0; k < BKK; ++k) {
            float a[TM], b[TN];
            float4 a0 = *reinterpret_cast<const float4*>(&As[k][ty * TM]);
            float4 a1 = *reinterpret_cast<const float4*>(&As[k][ty * TM + 4]);
            a[0] = a0.x; a[1] = a0.y; a[2] = a0.z; a[3] = a0.w;
            a[4] = a1.x; a[5] = a1.y; a[6] = a1.z; a[7] = a1.w;
            float4 b0 = *reinterpret_cast<const float4*>(&Bs[k][tx * TN]);
            float4 b1 = *reinterpret_cast<const float4*>(&Bs[k][tx * TN + 4]);
            b[0] = b0.x; b[1] = b0.y; b[2] = b0.z; b[3] = b0.w;
            b[4] = b1.x; b[5] = b1.y; b[6] = b1.z; b[7] = b1.w;
#pragma unroll
            for (int i = 0; i < TM; ++i)
#pragma unroll
                for (int j = 0; j < TN; ++j) acc[i][j] += a[i] * b[j];
        }
        __syncthreads();
    }

    // epilogue: bias + (optional) exact-erf GELU, vectorized stores
    float bv[TN];
#pragma unroll
    for (int j = 0; j < TN; ++j) bv[j] = bias[n0 + tx * TN + j];
#pragma unroll
    for (int i = 0; i < TM; ++i) {
        int row = m0 + ty * TM + i;
        float v[TN];
#pragma unroll
        for (int j = 0; j < TN; ++j) {
            float t = acc[i][j] + bv[j];
            if (GELU) t = 0.5f * t * (1.0f + erff(t * 0.7071067811865475f));
            v[j] = t;
        }
        float4* out = reinterpret_cast<float4*>(&Y[(size_t)row * HID + n0 + tx * TN]);
        out[0] = make_float4(v[0], v[1], v[2], v[3]);
        out[1] = make_float4(v[4], v[5], v[6], v[7]);
    }
}

// ---------------------------------------------------------------------------
// Final: warp per particle: 256->9 + symmetrize + P=R@x, cauchy=P@F^T
// ---------------------------------------------------------------------------
__global__ __launch_bounds__(256)
void final_kernel(const float* __restrict__ X4, const float* __restrict__ W5,
                  const float* __restrict__ b5, const float* __restrict__ F,
                  float* __restrict__ out, int B) {
    __shared__ float W5s[256 * 9];
    __shared__ float b5s[9];
    int tid = threadIdx.x;
    for (int i = tid; i < 256 * 9; i += 256) W5s[i] = W5[i];
    if (tid < 9) b5s[tid] = b5[tid];
    __syncthreads();

    int warp = tid >> 5, lane = tid & 31;
    int p = blockIdx.x * 8 + warp;
    if (p >= B) return;

    const float* xr = X4 + (size_t)p * HID;
    float acc[9];
#pragma unroll
    for (int j = 0; j < 9; ++j) acc[j] = 0.0f;
#pragma unroll
    for (int t = 0; t < 8; ++t) {
        int k = lane + 32 * t;
        float x = xr[k];
#pragma unroll
        for (int j = 0; j < 9; ++j) acc[j] += x * W5s[k * 9 + j];
    }
#pragma unroll
    for (int j = 0; j < 9; ++j) {
#pragma unroll
        for (int o = 16; o >= 1; o >>= 1)
            acc[j] += __shfl_xor_sync(0xffffffffu, acc[j], o);
    }

    if (lane == 0) {
        float x[3][3], xs[3][3], Rm[3][3], Fm[3][3], P[3][3];
#pragma unroll
        for (int i = 0; i < 3; ++i)
#pragma unroll
            for (int j = 0; j < 3; ++j) {
                x[i][j]  = acc[i * 3 + j] + b5s[i * 3 + j];
                Rm[i][j] = g_R[(size_t)p * 9 + i * 3 + j];
                Fm[i][j] = F[(size_t)p * 9 + i * 3 + j];
            }
#pragma unroll
        for (int i = 0; i < 3; ++i)
#pragma unroll
            for (int j = 0; j < 3; ++j) xs[i][j] = 0.5f * (x[i][j] + x[j][i]);
#pragma unroll
        for (int i = 0; i < 3; ++i)
#pragma unroll
            for (int j = 0; j < 3; ++j)
                P[i][j] = Rm[i][0] * xs[0][j] + Rm[i][1] * xs[1][j] + Rm[i][2] * xs[2][j];
        // cauchy = P @ F^T
#pragma unroll
        for (int i = 0; i < 3; ++i)
#pragma unroll
            for (int j = 0; j < 3; ++j)
                out[(size_t)p * 9 + i * 3 + j] =
                    P[i][0] * Fm[j][0] + P[i][1] * Fm[j][1] + P[i][2] * Fm[j][2];
    }
}

// ---------------------------------------------------------------------------
extern "C" void kernel_launch(void* const* d_in, const int* in_sizes, int n_in,
                              void* d_out, int out_size) {
    const float* F    = (const float*)d_in[0];
    const float* C    = (const float*)d_in[1];
    const float* emb  = (const float*)d_in[2];
    const int*   traj = (const int*)d_in[3];
    const float* W1   = (const float*)d_in[4];
    const float* b1   = (const float*)d_in[5];
    const float* W2   = (const float*)d_in[6];
    const float* b2   = (const float*)d_in[7];
    const float* W3   = (const float*)d_in[8];
    const float* b3   = (const float*)d_in[9];
    const float* W4   = (const float*)d_in[10];
    const float* b4   = (const float*)d_in[11];
    const float* W5   = (const float*)d_in[12];
    const float* b5   = (const float*)d_in[13];
    float* out = (float*)d_out;

    int B = in_sizes[0] / 9;
    if (B > MAXB) B = MAXB;

    void *pX0, *pA, *pB, *pW1p, *pb1p;
    cudaGetSymbolAddress(&pX0, g_X0);
    cudaGetSymbolAddress(&pA, g_actA);
    cudaGetSymbolAddress(&pB, g_actB);
    cudaGetSymbolAddress(&pW1p, g_W1p);
    cudaGetSymbolAddress(&pb1p, g_b1p);

    prep_weights_kernel<<<1, 256>>>(emb, traj, W1, b1);
    prep_part_kernel<<<(B + 255) / 256, 256>>>(F, C, B);

    dim3 grid(HID / BN, B / BM);
    gemm_bias_act_kernel<32, true><<<grid, 256>>>(
        (const float*)pX0, (const float*)pW1p, (const float*)pb1p, (float*)pA);
    gemm_bias_act_kernel<256, true><<<grid, 256>>>(
        (const float*)pA, W2, b2, (float*)pB);
    gemm_bias_act_kernel<256, true><<<grid, 256>>>(
        (const float*)pB, W3, b3, (float*)pA);
    gemm_bias_act_kernel<256, true><<<grid, 256>>>(
        (const float*)pA, W4, b4, (float*)pB);

    final_kernel<<<(B + 7) / 8, 256>>>((const float*)pB, W5, b5, F, out, B);
}

// round 4
// speedup vs baseline: 1.9207x; 1.9207x over previous
#include <cuda_runtime.h>
#include <cuda_bf16.h>
#include <math.h>
#include <math_constants.h>
#include <stdint.h>

// ============================================================================
// StressNNEval — round 4: mma.sync bf16x3 (baseline PTX; compute_103-safe).
//   prep: fold latent into b1; split W2..W4 into bf16 hi/lo transposed [n][k]
//   layer1: fp32 SGEMM (K=32), epilogue writes activations as bf16 hi/lo
//   layers 2-4: mma.sync m16n8k16 bf16, 3 split terms, CTA tile 128x256
//   final: warp-per-particle 256->9 + symmetrize + R@x@F^T
// ============================================================================

#define MAXB 262144
#define HID  256

__device__ __align__(128) float g_X0[(size_t)MAXB * 32];
__device__ __align__(128) float g_R[(size_t)MAXB * 9];
__device__ __align__(128) float g_W1p[32 * HID];
__device__ __align__(128) float g_b1p[HID];
// activation ping-pong, split bf16 hi/lo
__device__ __align__(128) __nv_bfloat16 g_actH0[(size_t)MAXB * HID];
__device__ __align__(128) __nv_bfloat16 g_actL0[(size_t)MAXB * HID];
__device__ __align__(128) __nv_bfloat16 g_actH1[(size_t)MAXB * HID];
__device__ __align__(128) __nv_bfloat16 g_actL1[(size_t)MAXB * HID];
// W2..W4 transposed [n][k], split hi/lo
__device__ __align__(128) __nv_bfloat16 g_wtH[3 * 65536];
__device__ __align__(128) __nv_bfloat16 g_wtL[3 * 65536];

// ---------------------------------------------------------------------------
__device__ __forceinline__ uint32_t smem_u32(const void* p) {
    uint32_t a;
    asm("{ .reg .u64 t; cvta.to.shared.u64 t, %1; cvt.u32.u64 %0, t; }"
        : "=r"(a) : "l"(p));
    return a;
}
#define CP_ASYNC16(dst, src) \
    asm volatile("cp.async.cg.shared.global [%0], [%1], 16;" :: "r"(dst), "l"(src))
#define CP_COMMIT()  asm volatile("cp.async.commit_group;" ::: "memory")
#define CP_WAIT(n)   asm volatile("cp.async.wait_group %0;" :: "n"(n) : "memory")

#define LDSM4(r, addr)                                                        \
    asm volatile("ldmatrix.sync.aligned.m8n8.x4.shared.b16 {%0,%1,%2,%3}, [%4];" \
        : "=r"((r)[0]), "=r"((r)[1]), "=r"((r)[2]), "=r"((r)[3]) : "r"(addr))

#define MMA_BF16(c, a, b)                                                     \
    asm volatile("mma.sync.aligned.m16n8k16.row.col.f32.bf16.bf16.f32 "       \
        "{%0,%1,%2,%3}, {%4,%5,%6,%7}, {%8,%9}, {%0,%1,%2,%3};"               \
        : "+f"((c)[0]), "+f"((c)[1]), "+f"((c)[2]), "+f"((c)[3])              \
        : "r"((a)[0]), "r"((a)[1]), "r"((a)[2]), "r"((a)[3]),                 \
          "r"((b)[0]), "r"((b)[1]))

// ---------------------------------------------------------------------------
// prep: fold latent into bias; pad W1
// ---------------------------------------------------------------------------
__global__ void prep_weights_kernel(const float* __restrict__ emb,
                                    const int* __restrict__ traj,
                                    const float* __restrict__ W1,
                                    const float* __restrict__ b1) {
    int j = threadIdx.x;
    int t = traj[0];
    const float* e = emb + (size_t)t * 128;
    float s = b1[j];
#pragma unroll 4
    for (int k = 0; k < 128; ++k)
        s += e[k] * W1[(size_t)(25 + k) * HID + j];
    g_b1p[j] = s;
#pragma unroll
    for (int r = 0; r < 32; ++r)
        g_W1p[r * HID + j] = (r < 25) ? W1[(size_t)r * HID + j] : 0.0f;
}

// ---------------------------------------------------------------------------
// prep: W[k][n] fp32 -> wt[n][k] bf16 hi/lo
// ---------------------------------------------------------------------------
__global__ void prep_wsplit_kernel(const float* __restrict__ W, int layer) {
    int idx = blockIdx.x * blockDim.x + threadIdx.x;   // k*256+n
    int k = idx >> 8, n = idx & 255;
    float w = W[idx];
    __nv_bfloat16 hi = __float2bfloat16_rn(w);
    __nv_bfloat16 lo = __float2bfloat16_rn(w - __bfloat162float(hi));
    g_wtH[layer * 65536 + n * 256 + k] = hi;
    g_wtL[layer * 65536 + n * 256 + k] = lo;
}

// ---------------------------------------------------------------------------
// Per-particle invariants + polar rotation (fp32)
// ---------------------------------------------------------------------------
__global__ void prep_part_kernel(const float* __restrict__ F,
                                 const float* __restrict__ C, int B) {
    int p = blockIdx.x * blockDim.x + threadIdx.x;
    if (p >= B) return;

    float Fm[3][3];
#pragma unroll
    for (int i = 0; i < 3; ++i)
#pragma unroll
        for (int j = 0; j < 3; ++j)
            Fm[i][j] = F[(size_t)p * 9 + i * 3 + j];

    float G[3][3];
#pragma unroll
    for (int i = 0; i < 3; ++i)
#pragma unroll
        for (int j = 0; j < 3; ++j)
            G[i][j] = Fm[0][i] * Fm[0][j] + Fm[1][i] * Fm[1][j] + Fm[2][i] * Fm[2][j];

    float q  = (G[0][0] + G[1][1] + G[2][2]) * (1.0f / 3.0f);
    float p1 = G[0][1] * G[0][1] + G[0][2] * G[0][2] + G[1][2] * G[1][2];
    float p2 = (G[0][0] - q) * (G[0][0] - q) + (G[1][1] - q) * (G[1][1] - q) +
               (G[2][2] - q) * (G[2][2] - q) + 2.0f * p1;
    float e1, e2, e3;
    float pp = sqrtf(p2 * (1.0f / 6.0f));
    if (pp < 1e-20f) {
        e1 = e2 = e3 = q;
    } else {
        float ip = 1.0f / pp;
        float b00 = (G[0][0] - q) * ip, b11 = (G[1][1] - q) * ip, b22 = (G[2][2] - q) * ip;
        float b01 = G[0][1] * ip, b02 = G[0][2] * ip, b12 = G[1][2] * ip;
        float detB = b00 * (b11 * b22 - b12 * b12) - b01 * (b01 * b22 - b12 * b02) +
                     b02 * (b01 * b12 - b11 * b02);
        float r = fminf(1.0f, fmaxf(-1.0f, detB * 0.5f));
        float phi = acosf(r) * (1.0f / 3.0f);
        e1 = q + 2.0f * pp * cosf(phi);
        e3 = q + 2.0f * pp * cosf(phi + 2.0943951023931953f);
        e2 = 3.0f * q - e1 - e3;
    }
    float s1 = sqrtf(fmaxf(e1, 0.0f));
    float s2 = sqrtf(fmaxf(e2, 0.0f));
    float s3 = sqrtf(fmaxf(e3, 0.0f));

    float detF = Fm[0][0] * (Fm[1][1] * Fm[2][2] - Fm[1][2] * Fm[2][1]) -
                 Fm[0][1] * (Fm[1][0] * Fm[2][2] - Fm[1][2] * Fm[2][0]) +
                 Fm[0][2] * (Fm[1][0] * Fm[2][1] - Fm[1][1] * Fm[2][0]);

    float X[3][3];
#pragma unroll
    for (int i = 0; i < 3; ++i)
#pragma unroll
        for (int j = 0; j < 3; ++j) X[i][j] = Fm[i][j];
#pragma unroll
    for (int it = 0; it < 8; ++it) {
        float c00 = X[1][1] * X[2][2] - X[1][2] * X[2][1];
        float c01 = X[1][2] * X[2][0] - X[1][0] * X[2][2];
        float c02 = X[1][0] * X[2][1] - X[1][1] * X[2][0];
        float c10 = X[0][2] * X[2][1] - X[0][1] * X[2][2];
        float c11 = X[0][0] * X[2][2] - X[0][2] * X[2][0];
        float c12 = X[0][1] * X[2][0] - X[0][0] * X[2][1];
        float c20 = X[0][1] * X[1][2] - X[0][2] * X[1][1];
        float c21 = X[0][2] * X[1][0] - X[0][0] * X[1][2];
        float c22 = X[0][0] * X[1][1] - X[0][1] * X[1][0];
        float d   = X[0][0] * c00 + X[0][1] * c01 + X[0][2] * c02;
        float id  = 0.5f / d;
        X[0][0] = 0.5f * X[0][0] + id * c00;  X[0][1] = 0.5f * X[0][1] + id * c01;
        X[0][2] = 0.5f * X[0][2] + id * c02;  X[1][0] = 0.5f * X[1][0] + id * c10;
        X[1][1] = 0.5f * X[1][1] + id * c11;  X[1][2] = 0.5f * X[1][2] + id * c12;
        X[2][0] = 0.5f * X[2][0] + id * c20;  X[2][1] = 0.5f * X[2][1] + id * c21;
        X[2][2] = 0.5f * X[2][2] + id * c22;
    }
#pragma unroll
    for (int i = 0; i < 3; ++i)
#pragma unroll
        for (int j = 0; j < 3; ++j)
            g_R[(size_t)p * 9 + i * 3 + j] = X[i][j];

    float* x0 = g_X0 + (size_t)p * 32;
    x0[0] = s1 - 1.0f;  x0[1] = s2 - 1.0f;  x0[2] = s3 - 1.0f;
#pragma unroll
    for (int i = 0; i < 3; ++i)
#pragma unroll
        for (int j = 0; j < 3; ++j)
            x0[3 + i * 3 + j] = G[i][j] - ((i == j) ? 1.0f : 0.0f);
    x0[12] = detF - 1.0f;
    x0[13] = logf(detF) - 1.0f;
    float f00 = fmaxf(Fm[0][0], 1e-6f);
    x0[14] = f00 - 1.0f;
    x0[15] = logf(f00) - 1.0f;
#pragma unroll
    for (int k = 0; k < 9; ++k) x0[16 + k] = C[(size_t)p * 9 + k];
#pragma unroll
    for (int k = 25; k < 32; ++k) x0[k] = 0.0f;
}

// ---------------------------------------------------------------------------
// Layer-1 fp32 SGEMM (K=32), bias + erf GELU, outputs split bf16 hi/lo
// ---------------------------------------------------------------------------
#define BM 128
#define BN 128
#define BKK 16
#define TM 8
#define TN 8

__global__ __launch_bounds__(256, 2)
void gemm_l1_kernel(const float* __restrict__ A, const float* __restrict__ W,
                    const float* __restrict__ bias,
                    __nv_bfloat16* __restrict__ oH, __nv_bfloat16* __restrict__ oL) {
    const int K = 32;
    __shared__ float As[BKK][BM + 4];
    __shared__ float Bs[BKK][BN];
    const int m0 = blockIdx.y * BM, n0 = blockIdx.x * BN;
    const int tid = threadIdx.x, tx = tid & 15, ty = tid >> 4;

    float acc[TM][TN];
#pragma unroll
    for (int i = 0; i < TM; ++i)
#pragma unroll
        for (int j = 0; j < TN; ++j) acc[i][j] = 0.0f;

    for (int kk = 0; kk < K; kk += BKK) {
#pragma unroll
        for (int l = 0; l < 2; ++l) {
            int idx = tid + l * 256, row = idx >> 2, c4 = (idx & 3) << 2;
            float4 v = *reinterpret_cast<const float4*>(&A[(size_t)(m0 + row) * K + kk + c4]);
            As[c4 + 0][row] = v.x; As[c4 + 1][row] = v.y;
            As[c4 + 2][row] = v.z; As[c4 + 3][row] = v.w;
        }
#pragma unroll
        for (int l = 0; l < 2; ++l) {
            int idx = tid + l * 256, krow = idx >> 5, c4 = (idx & 31) << 2;
            *reinterpret_cast<float4*>(&Bs[krow][c4]) =
                *reinterpret_cast<const float4*>(&W[(size_t)(kk + krow) * HID + n0 + c4]);
        }
        __syncthreads();
#pragma unroll
        for (int k = 0; k < BKK; ++k) {
            float a[TM], b[TN];
            float4 a0 = *reinterpret_cast<const float4*>(&As[k][ty * TM]);
            float4 a1 = *reinterpret_cast<const float4*>(&As[k][ty * TM + 4]);
            a[0]=a0.x; a[1]=a0.y; a[2]=a0.z; a[3]=a0.w; a[4]=a1.x; a[5]=a1.y; a[6]=a1.z; a[7]=a1.w;
            float4 b0 = *reinterpret_cast<const float4*>(&Bs[k][tx * TN]);
            float4 b1 = *reinterpret_cast<const float4*>(&Bs[k][tx * TN + 4]);
            b[0]=b0.x; b[1]=b0.y; b[2]=b0.z; b[3]=b0.w; b[4]=b1.x; b[5]=b1.y; b[6]=b1.z; b[7]=b1.w;
#pragma unroll
            for (int i = 0; i < TM; ++i)
#pragma unroll
                for (int j = 0; j < TN; ++j) acc[i][j] += a[i] * b[j];
        }
        __syncthreads();
    }
    float bv[TN];
#pragma unroll
    for (int j = 0; j < TN; ++j) bv[j] = bias[n0 + tx * TN + j];
#pragma unroll
    for (int i = 0; i < TM; ++i) {
        int row = m0 + ty * TM + i;
        float v[TN];
#pragma unroll
        for (int j = 0; j < TN; ++j) {
            float t = acc[i][j] + bv[j];
            v[j] = 0.5f * t * (1.0f + erff(t * 0.7071067811865475f));
        }
        uint32_t hp[4], lp[4];
#pragma unroll
        for (int j2 = 0; j2 < 4; ++j2) {
            __nv_bfloat162 hh = __floats2bfloat162_rn(v[2 * j2], v[2 * j2 + 1]);
            float l0 = v[2 * j2]     - __bfloat162float(__low2bfloat16(hh));
            float l1 = v[2 * j2 + 1] - __bfloat162float(__high2bfloat16(hh));
            __nv_bfloat162 ll = __floats2bfloat162_rn(l0, l1);
            hp[j2] = *reinterpret_cast<uint32_t*>(&hh);
            lp[j2] = *reinterpret_cast<uint32_t*>(&ll);
        }
        size_t off = (size_t)row * HID + n0 + tx * TN;
        *reinterpret_cast<uint4*>(oH + off) = make_uint4(hp[0], hp[1], hp[2], hp[3]);
        *reinterpret_cast<uint4*>(oL + off) = make_uint4(lp[0], lp[1], lp[2], lp[3]);
    }
}

// ---------------------------------------------------------------------------
// mma.sync bf16x3 GEMM: Y[128tile, 256] = GELU(X @ W + b), split output
// smem: double-buffered stages (aH,aL:128x(32+pad), wH,wL:256x(32+pad)) + bias
// A/W smem rows are 80B (64B data + 16B pad): 80 mod 128 cycles bank groups
// -> conflict-free ldmatrix without XOR swizzle.
// ---------------------------------------------------------------------------
#define AH_OFF   0
#define AL_OFF   10240
#define WH_OFF   20480
#define WL_OFF   40960
#define STAGE_SZ 61440
#define BIAS_OFF 122880
#define SMEM_TOT 123904
#define STG_STRIDE 528

__global__ __launch_bounds__(512, 1)
void gemm_mma_kernel(const __nv_bfloat16* __restrict__ aH,
                     const __nv_bfloat16* __restrict__ aL,
                     const __nv_bfloat16* __restrict__ wH,
                     const __nv_bfloat16* __restrict__ wL,
                     const float* __restrict__ bias,
                     __nv_bfloat16* __restrict__ oH,
                     __nv_bfloat16* __restrict__ oL) {
    extern __shared__ char smem[];
    const uint32_t sb = smem_u32(smem);
    const int tid = threadIdx.x, lane = tid & 31, warp = tid >> 5;
    const int rm = (warp & 3) * 32;        // warp row base (0..96)
    const int cn = (warp >> 2) * 64;       // warp col base (0..192)
    const size_t grow0 = (size_t)blockIdx.x * 128;

    if (tid < 256)
        *reinterpret_cast<float*>(smem + BIAS_OFF + tid * 4) = bias[tid];

    float acc[2][8][4];
#pragma unroll
    for (int mt = 0; mt < 2; ++mt)
#pragma unroll
        for (int n8 = 0; n8 < 8; ++n8)
#pragma unroll
            for (int r = 0; r < 4; ++r) acc[mt][n8][r] = 0.0f;

    // lane-invariant ldmatrix base offsets
    const uint32_t a_off = (uint32_t)(rm + (lane & 15)) * 80u + ((lane >> 4) << 4);
    const uint32_t w_off =
        (uint32_t)(cn + ((lane >> 4) << 3) + (lane & 7)) * 80u + (((lane >> 3) & 1) << 4);

    // ---- async stage loader (3072 x 16B chunks, 6 per thread) ----
    auto issue_stage = [&](int kk, int stage) {
        const uint32_t stg = sb + (uint32_t)stage * STAGE_SZ;
#pragma unroll
        for (int j = 0; j < 6; ++j) {
            int q = tid + j * 512;
            uint32_t dst;
            const __nv_bfloat16* src;
            if (q < 512) {
                int r = q >> 2, c = q & 3;
                dst = stg + AH_OFF + r * 80 + c * 16;
                src = aH + ((grow0 + r) << 8) + kk + c * 8;
            } else if (q < 1024) {
                int i = q - 512, r = i >> 2, c = i & 3;
                dst = stg + AL_OFF + r * 80 + c * 16;
                src = aL + ((grow0 + r) << 8) + kk + c * 8;
            } else if (q < 2048) {
                int i = q - 1024, n = i >> 2, c = i & 3;
                dst = stg + WH_OFF + n * 80 + c * 16;
                src = wH + n * 256 + kk + c * 8;
            } else {
                int i = q - 2048, n = i >> 2, c = i & 3;
                dst = stg + WL_OFF + n * 80 + c * 16;
                src = wL + n * 256 + kk + c * 8;
            }
            CP_ASYNC16(dst, src);
        }
        CP_COMMIT();
    };

    issue_stage(0, 0);

    for (int ch = 0; ch < 8; ++ch) {
        if (ch < 7) {
            issue_stage((ch + 1) * 32, (ch + 1) & 1);
            CP_WAIT(1);
        } else {
            CP_WAIT(0);
        }
        __syncthreads();

        const uint32_t stg = sb + (uint32_t)(ch & 1) * STAGE_SZ;
#pragma unroll
        for (int ks = 0; ks < 2; ++ks) {
            uint32_t ah[2][4], al[2][4], bw[8][2];
#pragma unroll
            for (int mt = 0; mt < 2; ++mt) {
                LDSM4(ah[mt], stg + AH_OFF + a_off + mt * 1280 + ks * 32);
                LDSM4(al[mt], stg + AL_OFF + a_off + mt * 1280 + ks * 32);
            }
#pragma unroll
            for (int ng = 0; ng < 4; ++ng) {
                uint32_t r4[4];
                LDSM4(r4, stg + WH_OFF + w_off + ng * 1280 + ks * 32);
                bw[2 * ng][0] = r4[0]; bw[2 * ng][1] = r4[1];
                bw[2 * ng + 1][0] = r4[2]; bw[2 * ng + 1][1] = r4[3];
            }
#pragma unroll
            for (int mt = 0; mt < 2; ++mt)
#pragma unroll
                for (int n8 = 0; n8 < 8; ++n8) MMA_BF16(acc[mt][n8], ah[mt], bw[n8]);
#pragma unroll
            for (int mt = 0; mt < 2; ++mt)
#pragma unroll
                for (int n8 = 0; n8 < 8; ++n8) MMA_BF16(acc[mt][n8], al[mt], bw[n8]);
#pragma unroll
            for (int ng = 0; ng < 4; ++ng) {
                uint32_t r4[4];
                LDSM4(r4, stg + WL_OFF + w_off + ng * 1280 + ks * 32);
                bw[2 * ng][0] = r4[0]; bw[2 * ng][1] = r4[1];
                bw[2 * ng + 1][0] = r4[2]; bw[2 * ng + 1][1] = r4[3];
            }
#pragma unroll
            for (int mt = 0; mt < 2; ++mt)
#pragma unroll
                for (int n8 = 0; n8 < 8; ++n8) MMA_BF16(acc[mt][n8], ah[mt], bw[n8]);
        }
        __syncthreads();
    }

    // ---- epilogue: bias + erf GELU (pass 0 -> hi), pass 1 -> lo ----
    const int r_l = lane >> 2, c_l = (lane & 3) << 1;
#pragma unroll 1
    for (int pass = 0; pass < 2; ++pass) {
#pragma unroll
        for (int mt = 0; mt < 2; ++mt)
#pragma unroll
            for (int n8 = 0; n8 < 8; ++n8) {
                int row = rm + mt * 16 + r_l;
                int col = cn + n8 * 8 + c_l;
                float* a4 = acc[mt][n8];
                if (pass == 0) {
                    float b0 = *reinterpret_cast<float*>(smem + BIAS_OFF + col * 4);
                    float b1 = *reinterpret_cast<float*>(smem + BIAS_OFF + (col + 1) * 4);
                    float t;
                    t = a4[0] + b0; a4[0] = 0.5f * t * (1.0f + erff(t * 0.7071067811865475f));
                    t = a4[1] + b1; a4[1] = 0.5f * t * (1.0f + erff(t * 0.7071067811865475f));
                    t = a4[2] + b0; a4[2] = 0.5f * t * (1.0f + erff(t * 0.7071067811865475f));
                    t = a4[3] + b1; a4[3] = 0.5f * t * (1.0f + erff(t * 0.7071067811865475f));
                }
                uint32_t u0, u1;
                if (pass == 0) {
                    __nv_bfloat162 p0 = __floats2bfloat162_rn(a4[0], a4[1]);
                    __nv_bfloat162 p1 = __floats2bfloat162_rn(a4[2], a4[3]);
                    u0 = *reinterpret_cast<uint32_t*>(&p0);
                    u1 = *reinterpret_cast<uint32_t*>(&p1);
                } else {
                    float l0 = a4[0] - __bfloat162float(__float2bfloat16_rn(a4[0]));
                    float l1 = a4[1] - __bfloat162float(__float2bfloat16_rn(a4[1]));
                    float l2 = a4[2] - __bfloat162float(__float2bfloat16_rn(a4[2]));
                    float l3 = a4[3] - __bfloat162float(__float2bfloat16_rn(a4[3]));
                    __nv_bfloat162 p0 = __floats2bfloat162_rn(l0, l1);
                    __nv_bfloat162 p1 = __floats2bfloat162_rn(l2, l3);
                    u0 = *reinterpret_cast<uint32_t*>(&p0);
                    u1 = *reinterpret_cast<uint32_t*>(&p1);
                }
                *reinterpret_cast<uint32_t*>(smem + row * STG_STRIDE + col * 2) = u0;
                *reinterpret_cast<uint32_t*>(smem + (row + 8) * STG_STRIDE + col * 2) = u1;
            }
        __syncthreads();
        __nv_bfloat16* dst = pass ? oL : oH;
#pragma unroll
        for (int j = 0; j < 8; ++j) {
            int q = tid + j * 512;               // 0..4095
            int row = q >> 5, c = q & 31;
            uint4 v = *reinterpret_cast<uint4*>(smem + row * STG_STRIDE + c * 16);
            *reinterpret_cast<uint4*>(
                reinterpret_cast<char*>(dst + ((grow0 + row) << 8)) + c * 16) = v;
        }
        __syncthreads();
    }
}

// ---------------------------------------------------------------------------
// Final: warp per particle: 256->9 + symmetrize + P=R@x, cauchy=P@F^T
// ---------------------------------------------------------------------------
__global__ __launch_bounds__(256)
void final_kernel(const __nv_bfloat16* __restrict__ aH,
                  const __nv_bfloat16* __restrict__ aL,
                  const float* __restrict__ W5, const float* __restrict__ b5,
                  const float* __restrict__ F, float* __restrict__ out, int B) {
    __shared__ float W5s[256 * 9];
    __shared__ float b5s[9];
    int tid = threadIdx.x;
    for (int i = tid; i < 256 * 9; i += 256) W5s[i] = W5[i];
    if (tid < 9) b5s[tid] = b5[tid];
    __syncthreads();

    int warp = tid >> 5, lane = tid & 31;
    int p = blockIdx.x * 8 + warp;
    if (p >= B) return;

    const __nv_bfloat16* xh = aH + (size_t)p * HID;
    const __nv_bfloat16* xl = aL + (size_t)p * HID;
    float acc[9];
#pragma unroll
    for (int j = 0; j < 9; ++j) acc[j] = 0.0f;
#pragma unroll
    for (int t = 0; t < 8; ++t) {
        int k = lane + 32 * t;
        float x = __bfloat162float(xh[k]) + __bfloat162float(xl[k]);
#pragma unroll
        for (int j = 0; j < 9; ++j) acc[j] += x * W5s[k * 9 + j];
    }
#pragma unroll
    for (int j = 0; j < 9; ++j) {
#pragma unroll
        for (int o = 16; o >= 1; o >>= 1)
            acc[j] += __shfl_xor_sync(0xffffffffu, acc[j], o);
    }

    if (lane == 0) {
        float x[3][3], xs[3][3], Rm[3][3], Fm[3][3], P[3][3];
#pragma unroll
        for (int i = 0; i < 3; ++i)
#pragma unroll
            for (int j = 0; j < 3; ++j) {
                x[i][j]  = acc[i * 3 + j] + b5s[i * 3 + j];
                Rm[i][j] = g_R[(size_t)p * 9 + i * 3 + j];
                Fm[i][j] = F[(size_t)p * 9 + i * 3 + j];
            }
#pragma unroll
        for (int i = 0; i < 3; ++i)
#pragma unroll
            for (int j = 0; j < 3; ++j) xs[i][j] = 0.5f * (x[i][j] + x[j][i]);
#pragma unroll
        for (int i = 0; i < 3; ++i)
#pragma unroll
            for (int j = 0; j < 3; ++j)
                P[i][j] = Rm[i][0] * xs[0][j] + Rm[i][1] * xs[1][j] + Rm[i][2] * xs[2][j];
#pragma unroll
        for (int i = 0; i < 3; ++i)
#pragma unroll
            for (int j = 0; j < 3; ++j)
                out[(size_t)p * 9 + i * 3 + j] =
                    P[i][0] * Fm[j][0] + P[i][1] * Fm[j][1] + P[i][2] * Fm[j][2];
    }
}

// ---------------------------------------------------------------------------
extern "C" void kernel_launch(void* const* d_in, const int* in_sizes, int n_in,
                              void* d_out, int out_size) {
    const float* F    = (const float*)d_in[0];
    const float* C    = (const float*)d_in[1];
    const float* emb  = (const float*)d_in[2];
    const int*   traj = (const int*)d_in[3];
    const float* W1   = (const float*)d_in[4];
    const float* b1   = (const float*)d_in[5];
    const float* W2   = (const float*)d_in[6];
    const float* b2   = (const float*)d_in[7];
    const float* W3   = (const float*)d_in[8];
    const float* b3   = (const float*)d_in[9];
    const float* W4   = (const float*)d_in[10];
    const float* b4   = (const float*)d_in[11];
    const float* W5   = (const float*)d_in[12];
    const float* b5   = (const float*)d_in[13];
    float* out = (float*)d_out;

    int B = in_sizes[0] / 9;
    if (B > MAXB) B = MAXB;

    void *pX0, *pW1p, *pb1p, *pH0, *pL0, *pH1, *pL1, *pWtH, *pWtL;
    cudaGetSymbolAddress(&pX0, g_X0);
    cudaGetSymbolAddress(&pW1p, g_W1p);
    cudaGetSymbolAddress(&pb1p, g_b1p);
    cudaGetSymbolAddress(&pH0, g_actH0);
    cudaGetSymbolAddress(&pL0, g_actL0);
    cudaGetSymbolAddress(&pH1, g_actH1);
    cudaGetSymbolAddress(&pL1, g_actL1);
    cudaGetSymbolAddress(&pWtH, g_wtH);
    cudaGetSymbolAddress(&pWtL, g_wtL);

    static bool attr_set = false;
    if (!attr_set) {
        cudaFuncSetAttribute(gemm_mma_kernel,
                             cudaFuncAttributeMaxDynamicSharedMemorySize, SMEM_TOT);
        attr_set = true;
    }

    prep_weights_kernel<<<1, 256>>>(emb, traj, W1, b1);
    prep_wsplit_kernel<<<256, 256>>>(W2, 0);
    prep_wsplit_kernel<<<256, 256>>>(W3, 1);
    prep_wsplit_kernel<<<256, 256>>>(W4, 2);
    prep_part_kernel<<<(B + 255) / 256, 256>>>(F, C, B);

    dim3 grid1(HID / BN, B / BM);
    gemm_l1_kernel<<<grid1, 256>>>((const float*)pX0, (const float*)pW1p,
                                   (const float*)pb1p,
                                   (__nv_bfloat16*)pH0, (__nv_bfloat16*)pL0);

    int ntiles = B / 128;
    const __nv_bfloat16* wtH = (const __nv_bfloat16*)pWtH;
    const __nv_bfloat16* wtL = (const __nv_bfloat16*)pWtL;

    gemm_mma_kernel<<<ntiles, 512, SMEM_TOT>>>(
        (const __nv_bfloat16*)pH0, (const __nv_bfloat16*)pL0,
        wtH + 0 * 65536, wtL + 0 * 65536, b2,
        (__nv_bfloat16*)pH1, (__nv_bfloat16*)pL1);
    gemm_mma_kernel<<<ntiles, 512, SMEM_TOT>>>(
        (const __nv_bfloat16*)pH1, (const __nv_bfloat16*)pL1,
        wtH + 1 * 65536, wtL + 1 * 65536, b3,
        (__nv_bfloat16*)pH0, (__nv_bfloat16*)pL0);
    gemm_mma_kernel<<<ntiles, 512, SMEM_TOT>>>(
        (const __nv_bfloat16*)pH0, (const __nv_bfloat16*)pL0,
        wtH + 2 * 65536, wtL + 2 * 65536, b4,
        (__nv_bfloat16*)pH1, (__nv_bfloat16*)pL1);

    final_kernel<<<(B + 7) / 8, 256>>>(
        (const __nv_bfloat16*)pH1, (const __nv_bfloat16*)pL1, W5, b5, F, out, B);
}

// round 5
// speedup vs baseline: 2.4435x; 1.2722x over previous
#include <cuda_runtime.h>
#include <cuda_bf16.h>
#include <math.h>
#include <math_constants.h>
#include <stdint.h>

// ============================================================================
// StressNNEval — round 5: FULLY FUSED network in one kernel.
//   prep_all : fold latent into b1; split W1p..W4 into bf16 hi/lo [n][k]
//   fused    : per 128-row tile: invariants+polar -> L1(K=32) -> L2..L4(K=256)
//              all via mma.sync bf16x3 with activations resident in SMEM,
//              weights streamed (double-buffered) via cp.async ->
//              L5 (256->9) + symmetrize + R@x@F^T, straight to out.
// ============================================================================

#define MAXB 262144
#define HID  256

__device__ __align__(128) float g_b1p[HID];
__device__ __align__(128) __nv_bfloat16 g_wt1H[32 * HID];
__device__ __align__(128) __nv_bfloat16 g_wt1L[32 * HID];
__device__ __align__(128) __nv_bfloat16 g_wtH[3 * HID * HID];
__device__ __align__(128) __nv_bfloat16 g_wtL[3 * HID * HID];

// ---- smem layout (dynamic, 222720 B) --------------------------------------
#define ACT_H    0              // 128 rows x 528B (256 bf16 + 16 pad)
#define ACT_L    67584
#define WSTG     135168         // 2 stages x (WH 20480 + WL 20480)
#define STAGE_SZ 40960
#define BIAS_OFF 217088         // 256 fp32
#define RBUF     218112         // 128 x 9 fp32
#define SMEM_TOT 222720
#define W5S      WSTG           // reused after mainloop: 256x9 fp32
#define B5S      (WSTG + 9216)

// ---------------------------------------------------------------------------
__device__ __forceinline__ uint32_t smem_u32(const void* p) {
    uint32_t a;
    asm("{ .reg .u64 t; cvta.to.shared.u64 t, %1; cvt.u32.u64 %0, t; }"
        : "=r"(a) : "l"(p));
    return a;
}
#define CP_ASYNC16(dst, src) \
    asm volatile("cp.async.cg.shared.global [%0], [%1], 16;" :: "r"(dst), "l"(src))
#define CP_COMMIT()  asm volatile("cp.async.commit_group;" ::: "memory")
#define CP_WAIT(n)   asm volatile("cp.async.wait_group %0;" :: "n"(n) : "memory")

#define LDSM4(r, addr)                                                        \
    asm volatile("ldmatrix.sync.aligned.m8n8.x4.shared.b16 {%0,%1,%2,%3}, [%4];" \
        : "=r"((r)[0]), "=r"((r)[1]), "=r"((r)[2]), "=r"((r)[3]) : "r"(addr))

#define MMA_BF16(c, a, b)                                                     \
    asm volatile("mma.sync.aligned.m16n8k16.row.col.f32.bf16.bf16.f32 "       \
        "{%0,%1,%2,%3}, {%4,%5,%6,%7}, {%8,%9}, {%0,%1,%2,%3};"               \
        : "+f"((c)[0]), "+f"((c)[1]), "+f"((c)[2]), "+f"((c)[3])              \
        : "r"((a)[0]), "r"((a)[1]), "r"((a)[2]), "r"((a)[3]),                 \
          "r"((b)[0]), "r"((b)[1]))

__device__ __forceinline__ float gelu_f(float t) {
    return 0.5f * t * (1.0f + erff(t * 0.7071067811865475f));
}

// ---------------------------------------------------------------------------
// prep_all: block 0 folds latent into b1; blocks 1..32 split padded W1;
//           blocks 33..800 split W2..W4 into transposed [n][k] hi/lo
// ---------------------------------------------------------------------------
__global__ void prep_all_kernel(const float* __restrict__ emb,
                                const int* __restrict__ traj,
                                const float* __restrict__ W1,
                                const float* __restrict__ b1,
                                const float* __restrict__ W2,
                                const float* __restrict__ W3,
                                const float* __restrict__ W4) {
    int bid = blockIdx.x, tid = threadIdx.x;
    if (bid == 0) {
        int t = traj[0];
        const float* e = emb + (size_t)t * 128;
        float s = b1[tid];
#pragma unroll 4
        for (int k = 0; k < 128; ++k)
            s += e[k] * W1[(size_t)(25 + k) * HID + tid];
        g_b1p[tid] = s;
    } else if (bid <= 32) {
        int idx = (bid - 1) * 256 + tid;       // 0..8191
        int n = idx >> 5, k = idx & 31;
        float v = (k < 25) ? W1[(size_t)k * HID + n] : 0.0f;
        __nv_bfloat16 hi = __float2bfloat16_rn(v);
        __nv_bfloat16 lo = __float2bfloat16_rn(v - __bfloat162float(hi));
        g_wt1H[n * 32 + k] = hi;
        g_wt1L[n * 32 + k] = lo;
    } else {
        int L = (bid - 33) >> 8;               // 0..2
        int idx = ((bid - 33) & 255) * 256 + tid;
        int k = idx >> 8, n = idx & 255;
        const float* W = (L == 0) ? W2 : ((L == 1) ? W3 : W4);
        float v = W[(size_t)k * HID + n];
        __nv_bfloat16 hi = __float2bfloat16_rn(v);
        __nv_bfloat16 lo = __float2bfloat16_rn(v - __bfloat162float(hi));
        g_wtH[L * 65536 + n * 256 + k] = hi;
        g_wtL[L * 65536 + n * 256 + k] = lo;
    }
}

// ---------------------------------------------------------------------------
// THE fused kernel: one CTA per 128-row tile, 512 threads.
// ---------------------------------------------------------------------------
__global__ __launch_bounds__(512, 1)
void fused_kernel(const float* __restrict__ F, const float* __restrict__ C,
                  const float* __restrict__ b2, const float* __restrict__ b3,
                  const float* __restrict__ b4, const float* __restrict__ W5,
                  const float* __restrict__ b5, float* __restrict__ out) {
    extern __shared__ char smem[];
    const uint32_t sb = smem_u32(smem);
    const int tid = threadIdx.x, lane = tid & 31, warp = tid >> 5;
    const int rm = (warp & 3) * 32;            // warp row base
    const int cn = (warp >> 2) * 64;           // warp col base
    const int tile = blockIdx.x;

    // --- weight-chunk loader: 2048 x 16B (WH 20KB + WL 20KB), 4 per thread
    auto loadW = [&](const __nv_bfloat16* wh, const __nv_bfloat16* wl,
                     int K, int ch, uint32_t stg) {
        const uint32_t sbase = sb + WSTG + stg * STAGE_SZ;
#pragma unroll
        for (int j = 0; j < 4; ++j) {
            int q = tid + j * 512;             // 0..2047
            int half = q >> 10;                // 0=hi 1=lo
            int i = q & 1023;
            int n = i >> 2, c = i & 3;
            uint32_t dst = sbase + half * 20480 + n * 80 + c * 16;
            const __nv_bfloat16* src = (half ? wl : wh) + n * K + ch * 32 + c * 8;
            CP_ASYNC16(dst, src);
        }
        CP_COMMIT();
    };

    // prologue: prefetch L1 weights (chunk 0 -> stage 0), load L1 bias
    loadW(g_wt1H, g_wt1L, 32, 0, 0);
    if (tid < 256)
        *reinterpret_cast<float*>(smem + BIAS_OFF + tid * 4) = g_b1p[tid];

    // --- in-kernel prep: invariants + polar rotation -> X0 into ACT, R -> RBUF
    if (tid < 128) {
        int p = tile * 128 + tid;
        float Fm[3][3];
#pragma unroll
        for (int i = 0; i < 3; ++i)
#pragma unroll
            for (int j = 0; j < 3; ++j)
                Fm[i][j] = F[(size_t)p * 9 + i * 3 + j];

        float G[3][3];
#pragma unroll
        for (int i = 0; i < 3; ++i)
#pragma unroll
            for (int j = 0; j < 3; ++j)
                G[i][j] = Fm[0][i] * Fm[0][j] + Fm[1][i] * Fm[1][j] + Fm[2][i] * Fm[2][j];

        float q = (G[0][0] + G[1][1] + G[2][2]) * (1.0f / 3.0f);
        float p1 = G[0][1] * G[0][1] + G[0][2] * G[0][2] + G[1][2] * G[1][2];
        float p2 = (G[0][0] - q) * (G[0][0] - q) + (G[1][1] - q) * (G[1][1] - q) +
                   (G[2][2] - q) * (G[2][2] - q) + 2.0f * p1;
        float e1, e2, e3;
        float pp = sqrtf(p2 * (1.0f / 6.0f));
        if (pp < 1e-20f) {
            e1 = e2 = e3 = q;
        } else {
            float ip = 1.0f / pp;
            float b00 = (G[0][0] - q) * ip, b11 = (G[1][1] - q) * ip, b22 = (G[2][2] - q) * ip;
            float b01 = G[0][1] * ip, b02 = G[0][2] * ip, b12 = G[1][2] * ip;
            float detB = b00 * (b11 * b22 - b12 * b12) - b01 * (b01 * b22 - b12 * b02) +
                         b02 * (b01 * b12 - b11 * b02);
            float r = fminf(1.0f, fmaxf(-1.0f, detB * 0.5f));
            float phi = acosf(r) * (1.0f / 3.0f);
            e1 = q + 2.0f * pp * cosf(phi);
            e3 = q + 2.0f * pp * cosf(phi + 2.0943951023931953f);
            e2 = 3.0f * q - e1 - e3;
        }
        float s1 = sqrtf(fmaxf(e1, 0.0f));
        float s2 = sqrtf(fmaxf(e2, 0.0f));
        float s3 = sqrtf(fmaxf(e3, 0.0f));

        float detF = Fm[0][0] * (Fm[1][1] * Fm[2][2] - Fm[1][2] * Fm[2][1]) -
                     Fm[0][1] * (Fm[1][0] * Fm[2][2] - Fm[1][2] * Fm[2][0]) +
                     Fm[0][2] * (Fm[1][0] * Fm[2][1] - Fm[1][1] * Fm[2][0]);

        float X[3][3];
#pragma unroll
        for (int i = 0; i < 3; ++i)
#pragma unroll
            for (int j = 0; j < 3; ++j) X[i][j] = Fm[i][j];
#pragma unroll
        for (int it = 0; it < 8; ++it) {
            float c00 = X[1][1] * X[2][2] - X[1][2] * X[2][1];
            float c01 = X[1][2] * X[2][0] - X[1][0] * X[2][2];
            float c02 = X[1][0] * X[2][1] - X[1][1] * X[2][0];
            float c10 = X[0][2] * X[2][1] - X[0][1] * X[2][2];
            float c11 = X[0][0] * X[2][2] - X[0][2] * X[2][0];
            float c12 = X[0][1] * X[2][0] - X[0][0] * X[2][1];
            float c20 = X[0][1] * X[1][2] - X[0][2] * X[1][1];
            float c21 = X[0][2] * X[1][0] - X[0][0] * X[1][2];
            float c22 = X[0][0] * X[1][1] - X[0][1] * X[1][0];
            float d = X[0][0] * c00 + X[0][1] * c01 + X[0][2] * c02;
            float id = 0.5f / d;
            X[0][0] = 0.5f * X[0][0] + id * c00;  X[0][1] = 0.5f * X[0][1] + id * c01;
            X[0][2] = 0.5f * X[0][2] + id * c02;  X[1][0] = 0.5f * X[1][0] + id * c10;
            X[1][1] = 0.5f * X[1][1] + id * c11;  X[1][2] = 0.5f * X[1][2] + id * c12;
            X[2][0] = 0.5f * X[2][0] + id * c20;  X[2][1] = 0.5f * X[2][1] + id * c21;
            X[2][2] = 0.5f * X[2][2] + id * c22;
        }
#pragma unroll
        for (int i = 0; i < 9; ++i)
            *reinterpret_cast<float*>(smem + RBUF + tid * 36 + i * 4) = X[i / 3][i % 3];

        float x0[32];
        x0[0] = s1 - 1.0f;  x0[1] = s2 - 1.0f;  x0[2] = s3 - 1.0f;
#pragma unroll
        for (int i = 0; i < 3; ++i)
#pragma unroll
            for (int j = 0; j < 3; ++j)
                x0[3 + i * 3 + j] = G[i][j] - ((i == j) ? 1.0f : 0.0f);
        x0[12] = detF - 1.0f;
        x0[13] = logf(detF) - 1.0f;
        float f00 = fmaxf(Fm[0][0], 1e-6f);
        x0[14] = f00 - 1.0f;
        x0[15] = logf(f00) - 1.0f;
#pragma unroll
        for (int k = 0; k < 9; ++k) x0[16 + k] = C[(size_t)p * 9 + k];
#pragma unroll
        for (int k = 25; k < 32; ++k) x0[k] = 0.0f;

#pragma unroll
        for (int cp = 0; cp < 16; ++cp) {
            float v0 = x0[2 * cp], v1 = x0[2 * cp + 1];
            __nv_bfloat162 h = __floats2bfloat162_rn(v0, v1);
            float l0 = v0 - __bfloat162float(__low2bfloat16(h));
            float l1 = v1 - __bfloat162float(__high2bfloat16(h));
            __nv_bfloat162 lo = __floats2bfloat162_rn(l0, l1);
            *reinterpret_cast<uint32_t*>(smem + ACT_H + tid * 528 + cp * 4) =
                *reinterpret_cast<uint32_t*>(&h);
            *reinterpret_cast<uint32_t*>(smem + ACT_L + tid * 528 + cp * 4) =
                *reinterpret_cast<uint32_t*>(&lo);
        }
    }

    // --- mainloop: 25 global chunks = L1(1) + L2..L4(8 each) ---------------
    float acc[2][8][4];
#pragma unroll
    for (int mt = 0; mt < 2; ++mt)
#pragma unroll
        for (int n8 = 0; n8 < 8; ++n8)
#pragma unroll
            for (int r = 0; r < 4; ++r) acc[mt][n8][r] = 0.0f;

    const uint32_t a_off = (uint32_t)(rm + (lane & 15)) * 528u + ((lane >> 4) << 4);
    const uint32_t w_off =
        (uint32_t)(cn + ((lane >> 4) << 3) + (lane & 7)) * 80u + (((lane >> 3) & 1) << 4);

    uint32_t stg = 0;
#pragma unroll 1
    for (int gi = 0; gi < 25; ++gi) {
        // prefetch next chunk (layer l2 = (gi>>3)+1, chunk c2 = gi&7)
        if (gi + 1 < 25) {
            int l2 = (gi >> 3) + 1;
            int c2 = gi & 7;
            loadW(g_wtH + (l2 - 1) * 65536, g_wtL + (l2 - 1) * 65536, 256, c2, stg ^ 1);
            CP_WAIT(1);
        } else {
            CP_WAIT(0);
        }
        __syncthreads();

        const int ch = (gi == 0) ? 0 : ((gi - 1) & 7);
        const uint32_t acol = (uint32_t)ch * 64u;
        const uint32_t sW = sb + WSTG + stg * STAGE_SZ;

#pragma unroll
        for (int ks = 0; ks < 2; ++ks) {
            uint32_t ah[2][4], al[2][4], bw[8][2];
#pragma unroll
            for (int mt = 0; mt < 2; ++mt) {
                LDSM4(ah[mt], sb + ACT_H + a_off + mt * 8448 + acol + ks * 32);
                LDSM4(al[mt], sb + ACT_L + a_off + mt * 8448 + acol + ks * 32);
            }
#pragma unroll
            for (int ng = 0; ng < 4; ++ng) {
                uint32_t r4[4];
                LDSM4(r4, sW + w_off + ng * 1280 + ks * 32);
                bw[2 * ng][0] = r4[0]; bw[2 * ng][1] = r4[1];
                bw[2 * ng + 1][0] = r4[2]; bw[2 * ng + 1][1] = r4[3];
            }
#pragma unroll
            for (int mt = 0; mt < 2; ++mt)
#pragma unroll
                for (int n8 = 0; n8 < 8; ++n8) MMA_BF16(acc[mt][n8], ah[mt], bw[n8]);
#pragma unroll
            for (int mt = 0; mt < 2; ++mt)
#pragma unroll
                for (int n8 = 0; n8 < 8; ++n8) MMA_BF16(acc[mt][n8], al[mt], bw[n8]);
#pragma unroll
            for (int ng = 0; ng < 4; ++ng) {
                uint32_t r4[4];
                LDSM4(r4, sW + 20480 + w_off + ng * 1280 + ks * 32);
                bw[2 * ng][0] = r4[0]; bw[2 * ng][1] = r4[1];
                bw[2 * ng + 1][0] = r4[2]; bw[2 * ng + 1][1] = r4[3];
            }
#pragma unroll
            for (int mt = 0; mt < 2; ++mt)
#pragma unroll
                for (int n8 = 0; n8 < 8; ++n8) MMA_BF16(acc[mt][n8], ah[mt], bw[n8]);
        }
        __syncthreads();
        stg ^= 1;

        // --- layer boundary: GELU + split + write new act into SMEM --------
        const bool eol = (gi == 0) || (((gi - 1) & 7) == 7);
        if (eol) {
            const int l = (gi == 0) ? 0 : (((gi - 1) >> 3) + 1);
            const int r_l = lane >> 2, c_l = (lane & 3) << 1;
#pragma unroll
            for (int mt = 0; mt < 2; ++mt)
#pragma unroll
                for (int n8 = 0; n8 < 8; ++n8) {
                    int row = rm + mt * 16 + r_l;
                    int col = cn + n8 * 8 + c_l;
                    float* a4 = acc[mt][n8];
                    float b0 = *reinterpret_cast<float*>(smem + BIAS_OFF + col * 4);
                    float b1v = *reinterpret_cast<float*>(smem + BIAS_OFF + (col + 1) * 4);
                    float g0 = gelu_f(a4[0] + b0);
                    float g1 = gelu_f(a4[1] + b1v);
                    float g2 = gelu_f(a4[2] + b0);
                    float g3 = gelu_f(a4[3] + b1v);
                    __nv_bfloat162 h01 = __floats2bfloat162_rn(g0, g1);
                    __nv_bfloat162 h23 = __floats2bfloat162_rn(g2, g3);
                    float l0 = g0 - __bfloat162float(__low2bfloat16(h01));
                    float l1 = g1 - __bfloat162float(__high2bfloat16(h01));
                    float l2 = g2 - __bfloat162float(__low2bfloat16(h23));
                    float l3 = g3 - __bfloat162float(__high2bfloat16(h23));
                    __nv_bfloat162 q01 = __floats2bfloat162_rn(l0, l1);
                    __nv_bfloat162 q23 = __floats2bfloat162_rn(l2, l3);
                    *reinterpret_cast<uint32_t*>(smem + ACT_H + row * 528 + col * 2) =
                        *reinterpret_cast<uint32_t*>(&h01);
                    *reinterpret_cast<uint32_t*>(smem + ACT_H + (row + 8) * 528 + col * 2) =
                        *reinterpret_cast<uint32_t*>(&h23);
                    *reinterpret_cast<uint32_t*>(smem + ACT_L + row * 528 + col * 2) =
                        *reinterpret_cast<uint32_t*>(&q01);
                    *reinterpret_cast<uint32_t*>(smem + ACT_L + (row + 8) * 528 + col * 2) =
                        *reinterpret_cast<uint32_t*>(&q23);
                    a4[0] = a4[1] = a4[2] = a4[3] = 0.0f;
                }
            __syncthreads();
            if (l < 3 && tid < 256) {
                const float* nb = (l == 0) ? b2 : ((l == 1) ? b3 : b4);
                *reinterpret_cast<float*>(smem + BIAS_OFF + tid * 4) = nb[tid];
            }
        }
    }

    // --- final layer: 256 -> 9 + symmetrize + P=R@x, cauchy = P@F^T --------
    for (int i = tid; i < 2304; i += 512)
        *reinterpret_cast<float*>(smem + W5S + i * 4) = W5[i];
    if (tid < 9)
        *reinterpret_cast<float*>(smem + B5S + tid * 4) = b5[tid];
    __syncthreads();

#pragma unroll 1
    for (int rr = 0; rr < 8; ++rr) {
        int row = warp * 8 + rr;
        float s[9];
#pragma unroll
        for (int j = 0; j < 9; ++j) s[j] = 0.0f;
#pragma unroll
        for (int t4 = 0; t4 < 4; ++t4) {
            int cp = lane + 32 * t4;
            uint32_t hp = *reinterpret_cast<uint32_t*>(smem + ACT_H + row * 528 + cp * 4);
            uint32_t lp = *reinterpret_cast<uint32_t*>(smem + ACT_L + row * 528 + cp * 4);
            __nv_bfloat162 h = *reinterpret_cast<__nv_bfloat162*>(&hp);
            __nv_bfloat162 lo = *reinterpret_cast<__nv_bfloat162*>(&lp);
            float x0 = __bfloat162float(__low2bfloat16(h)) + __bfloat162float(__low2bfloat16(lo));
            float x1 = __bfloat162float(__high2bfloat16(h)) + __bfloat162float(__high2bfloat16(lo));
            const float* w0 = reinterpret_cast<const float*>(smem + W5S) + (2 * cp) * 9;
#pragma unroll
            for (int j = 0; j < 9; ++j) s[j] += x0 * w0[j] + x1 * w0[9 + j];
        }
#pragma unroll
        for (int j = 0; j < 9; ++j) {
#pragma unroll
            for (int o = 16; o >= 1; o >>= 1)
                s[j] += __shfl_xor_sync(0xffffffffu, s[j], o);
        }
        if (lane == 0) {
            int p = tile * 128 + row;
            float x[3][3], xs[3][3], Rm[3][3], Fm[3][3], P[3][3];
#pragma unroll
            for (int i = 0; i < 3; ++i)
#pragma unroll
                for (int j = 0; j < 3; ++j) {
                    x[i][j] = s[i * 3 + j] +
                              *reinterpret_cast<float*>(smem + B5S + (i * 3 + j) * 4);
                    Rm[i][j] = *reinterpret_cast<float*>(smem + RBUF + row * 36 + (i * 3 + j) * 4);
                    Fm[i][j] = F[(size_t)p * 9 + i * 3 + j];
                }
#pragma unroll
            for (int i = 0; i < 3; ++i)
#pragma unroll
                for (int j = 0; j < 3; ++j) xs[i][j] = 0.5f * (x[i][j] + x[j][i]);
#pragma unroll
            for (int i = 0; i < 3; ++i)
#pragma unroll
                for (int j = 0; j < 3; ++j)
                    P[i][j] = Rm[i][0] * xs[0][j] + Rm[i][1] * xs[1][j] + Rm[i][2] * xs[2][j];
#pragma unroll
            for (int i = 0; i < 3; ++i)
#pragma unroll
                for (int j = 0; j < 3; ++j)
                    out[(size_t)p * 9 + i * 3 + j] =
                        P[i][0] * Fm[j][0] + P[i][1] * Fm[j][1] + P[i][2] * Fm[j][2];
        }
    }
}

// ---------------------------------------------------------------------------
extern "C" void kernel_launch(void* const* d_in, const int* in_sizes, int n_in,
                              void* d_out, int out_size) {
    const float* F    = (const float*)d_in[0];
    const float* C    = (const float*)d_in[1];
    const float* emb  = (const float*)d_in[2];
    const int*   traj = (const int*)d_in[3];
    const float* W1   = (const float*)d_in[4];
    const float* b1   = (const float*)d_in[5];
    const float* W2   = (const float*)d_in[6];
    const float* b2   = (const float*)d_in[7];
    const float* W3   = (const float*)d_in[8];
    const float* b3   = (const float*)d_in[9];
    const float* W4   = (const float*)d_in[10];
    const float* b4   = (const float*)d_in[11];
    const float* W5   = (const float*)d_in[12];
    const float* b5   = (const float*)d_in[13];
    float* out = (float*)d_out;

    int B = in_sizes[0] / 9;
    if (B > MAXB) B = MAXB;

    static bool attr_set = false;
    if (!attr_set) {
        cudaFuncSetAttribute(fused_kernel,
                             cudaFuncAttributeMaxDynamicSharedMemorySize, SMEM_TOT);
        attr_set = true;
    }

    prep_all_kernel<<<801, 256>>>(emb, traj, W1, b1, W2, W3, W4);
    fused_kernel<<<B / 128, 512, SMEM_TOT>>>(F, C, b2, b3, b4, W5, b5, out);
}

// round 6
// speedup vs baseline: 2.4601x; 1.0068x over previous
#include <cuda_runtime.h>
#include <cuda_bf16.h>
#include <math.h>
#include <math_constants.h>
#include <stdint.h>

// ============================================================================
// StressNNEval — round 6: fused kernel, 256 threads / 8 warps, 64x64 warp tile.
//   Same algorithm as round 5 (bf16x3 mma.sync, acts resident in SMEM,
//   weights double-buffered from L2); bigger warp tiles give register
//   headroom for LDSM/MMA pipelining and fewer barrier participants.
// ============================================================================

#define MAXB 262144
#define HID  256

__device__ __align__(128) float g_b1p[HID];
__device__ __align__(128) __nv_bfloat16 g_wt1H[32 * HID];
__device__ __align__(128) __nv_bfloat16 g_wt1L[32 * HID];
__device__ __align__(128) __nv_bfloat16 g_wtH[3 * HID * HID];
__device__ __align__(128) __nv_bfloat16 g_wtL[3 * HID * HID];

// ---- smem layout (dynamic, 222720 B) --------------------------------------
#define ACT_H    0              // 128 rows x 528B (256 bf16 + 16 pad)
#define ACT_L    67584
#define WSTG     135168         // 2 stages x (WH 20480 + WL 20480)
#define STAGE_SZ 40960
#define BIAS_OFF 217088         // 256 fp32
#define RBUF     218112         // 128 x 9 fp32
#define SMEM_TOT 222720
#define W5S      WSTG           // reused after mainloop: 256x9 fp32
#define B5S      (WSTG + 9216)

// ---------------------------------------------------------------------------
__device__ __forceinline__ uint32_t smem_u32(const void* p) {
    uint32_t a;
    asm("{ .reg .u64 t; cvta.to.shared.u64 t, %1; cvt.u32.u64 %0, t; }"
        : "=r"(a) : "l"(p));
    return a;
}
#define CP_ASYNC16(dst, src) \
    asm volatile("cp.async.cg.shared.global [%0], [%1], 16;" :: "r"(dst), "l"(src))
#define CP_COMMIT()  asm volatile("cp.async.commit_group;" ::: "memory")
#define CP_WAIT(n)   asm volatile("cp.async.wait_group %0;" :: "n"(n) : "memory")

#define LDSM4(r, addr)                                                        \
    asm volatile("ldmatrix.sync.aligned.m8n8.x4.shared.b16 {%0,%1,%2,%3}, [%4];" \
        : "=r"((r)[0]), "=r"((r)[1]), "=r"((r)[2]), "=r"((r)[3]) : "r"(addr))

#define MMA_BF16(c, a, b)                                                     \
    asm volatile("mma.sync.aligned.m16n8k16.row.col.f32.bf16.bf16.f32 "       \
        "{%0,%1,%2,%3}, {%4,%5,%6,%7}, {%8,%9}, {%0,%1,%2,%3};"               \
        : "+f"((c)[0]), "+f"((c)[1]), "+f"((c)[2]), "+f"((c)[3])              \
        : "r"((a)[0]), "r"((a)[1]), "r"((a)[2]), "r"((a)[3]),                 \
          "r"((b)[0]), "r"((b)[1]))

__device__ __forceinline__ float gelu_f(float t) {
    return 0.5f * t * (1.0f + erff(t * 0.7071067811865475f));
}

// ---------------------------------------------------------------------------
// prep_all: block 0 folds latent into b1; blocks 1..32 split padded W1;
//           blocks 33..800 split W2..W4 into transposed [n][k] hi/lo
// ---------------------------------------------------------------------------
__global__ void prep_all_kernel(const float* __restrict__ emb,
                                const int* __restrict__ traj,
                                const float* __restrict__ W1,
                                const float* __restrict__ b1,
                                const float* __restrict__ W2,
                                const float* __restrict__ W3,
                                const float* __restrict__ W4) {
    int bid = blockIdx.x, tid = threadIdx.x;
    if (bid == 0) {
        int t = traj[0];
        const float* e = emb + (size_t)t * 128;
        float s = b1[tid];
#pragma unroll 4
        for (int k = 0; k < 128; ++k)
            s += e[k] * W1[(size_t)(25 + k) * HID + tid];
        g_b1p[tid] = s;
    } else if (bid <= 32) {
        int idx = (bid - 1) * 256 + tid;       // 0..8191
        int n = idx >> 5, k = idx & 31;
        float v = (k < 25) ? W1[(size_t)k * HID + n] : 0.0f;
        __nv_bfloat16 hi = __float2bfloat16_rn(v);
        __nv_bfloat16 lo = __float2bfloat16_rn(v - __bfloat162float(hi));
        g_wt1H[n * 32 + k] = hi;
        g_wt1L[n * 32 + k] = lo;
    } else {
        int L = (bid - 33) >> 8;               // 0..2
        int idx = ((bid - 33) & 255) * 256 + tid;
        int k = idx >> 8, n = idx & 255;
        const float* W = (L == 0) ? W2 : ((L == 1) ? W3 : W4);
        float v = W[(size_t)k * HID + n];
        __nv_bfloat16 hi = __float2bfloat16_rn(v);
        __nv_bfloat16 lo = __float2bfloat16_rn(v - __bfloat162float(hi));
        g_wtH[L * 65536 + n * 256 + k] = hi;
        g_wtL[L * 65536 + n * 256 + k] = lo;
    }
}

// ---------------------------------------------------------------------------
// Fused kernel: one CTA per 128-row tile, 256 threads, 8 warps, 64x64/warp.
// ---------------------------------------------------------------------------
__global__ __launch_bounds__(256, 1)
void fused_kernel(const float* __restrict__ F, const float* __restrict__ C,
                  const float* __restrict__ b2, const float* __restrict__ b3,
                  const float* __restrict__ b4, const float* __restrict__ W5,
                  const float* __restrict__ b5, float* __restrict__ out) {
    extern __shared__ char smem[];
    const uint32_t sb = smem_u32(smem);
    const int tid = threadIdx.x, lane = tid & 31, warp = tid >> 5;
    const int rm = (warp & 1) * 64;            // warp row base (0 or 64)
    const int cn = (warp >> 1) * 64;           // warp col base (0..192)
    const int tile = blockIdx.x;

    // --- weight-chunk loader: 2048 x 16B (WH 20KB + WL 20KB), 8 per thread
    auto loadW = [&](const __nv_bfloat16* wh, const __nv_bfloat16* wl,
                     int K, int ch, uint32_t stg) {
        const uint32_t sbase = sb + WSTG + stg * STAGE_SZ;
#pragma unroll
        for (int j = 0; j < 8; ++j) {
            int q = tid + j * 256;             // 0..2047
            int half = q >> 10;                // 0=hi 1=lo
            int i = q & 1023;
            int n = i >> 2, c = i & 3;
            uint32_t dst = sbase + half * 20480 + n * 80 + c * 16;
            const __nv_bfloat16* src = (half ? wl : wh) + n * K + ch * 32 + c * 8;
            CP_ASYNC16(dst, src);
        }
        CP_COMMIT();
    };

    // prologue: prefetch L1 weights (chunk 0 -> stage 0), load L1 bias
    loadW(g_wt1H, g_wt1L, 32, 0, 0);
    *reinterpret_cast<float*>(smem + BIAS_OFF + tid * 4) = g_b1p[tid];

    // --- in-kernel prep: invariants + polar rotation -> X0 into ACT, R -> RBUF
    if (tid < 128) {
        int p = tile * 128 + tid;
        float Fm[3][3];
#pragma unroll
        for (int i = 0; i < 3; ++i)
#pragma unroll
            for (int j = 0; j < 3; ++j)
                Fm[i][j] = F[(size_t)p * 9 + i * 3 + j];

        float G[3][3];
#pragma unroll
        for (int i = 0; i < 3; ++i)
#pragma unroll
            for (int j = 0; j < 3; ++j)
                G[i][j] = Fm[0][i] * Fm[0][j] + Fm[1][i] * Fm[1][j] + Fm[2][i] * Fm[2][j];

        float q = (G[0][0] + G[1][1] + G[2][2]) * (1.0f / 3.0f);
        float p1 = G[0][1] * G[0][1] + G[0][2] * G[0][2] + G[1][2] * G[1][2];
        float p2 = (G[0][0] - q) * (G[0][0] - q) + (G[1][1] - q) * (G[1][1] - q) +
                   (G[2][2] - q) * (G[2][2] - q) + 2.0f * p1;
        float e1, e2, e3;
        float pp = sqrtf(p2 * (1.0f / 6.0f));
        if (pp < 1e-20f) {
            e1 = e2 = e3 = q;
        } else {
            float ip = 1.0f / pp;
            float b00 = (G[0][0] - q) * ip, b11 = (G[1][1] - q) * ip, b22 = (G[2][2] - q) * ip;
            float b01 = G[0][1] * ip, b02 = G[0][2] * ip, b12 = G[1][2] * ip;
            float detB = b00 * (b11 * b22 - b12 * b12) - b01 * (b01 * b22 - b12 * b02) +
                         b02 * (b01 * b12 - b11 * b02);
            float r = fminf(1.0f, fmaxf(-1.0f, detB * 0.5f));
            float phi = acosf(r) * (1.0f / 3.0f);
            e1 = q + 2.0f * pp * cosf(phi);
            e3 = q + 2.0f * pp * cosf(phi + 2.0943951023931953f);
            e2 = 3.0f * q - e1 - e3;
        }
        float s1 = sqrtf(fmaxf(e1, 0.0f));
        float s2 = sqrtf(fmaxf(e2, 0.0f));
        float s3 = sqrtf(fmaxf(e3, 0.0f));

        float detF = Fm[0][0] * (Fm[1][1] * Fm[2][2] - Fm[1][2] * Fm[2][1]) -
                     Fm[0][1] * (Fm[1][0] * Fm[2][2] - Fm[1][2] * Fm[2][0]) +
                     Fm[0][2] * (Fm[1][0] * Fm[2][1] - Fm[1][1] * Fm[2][0]);

        float X[3][3];
#pragma unroll
        for (int i = 0; i < 3; ++i)
#pragma unroll
            for (int j = 0; j < 3; ++j) X[i][j] = Fm[i][j];
#pragma unroll
        for (int it = 0; it < 8; ++it) {
            float c00 = X[1][1] * X[2][2] - X[1][2] * X[2][1];
            float c01 = X[1][2] * X[2][0] - X[1][0] * X[2][2];
            float c02 = X[1][0] * X[2][1] - X[1][1] * X[2][0];
            float c10 = X[0][2] * X[2][1] - X[0][1] * X[2][2];
            float c11 = X[0][0] * X[2][2] - X[0][2] * X[2][0];
            float c12 = X[0][1] * X[2][0] - X[0][0] * X[2][1];
            float c20 = X[0][1] * X[1][2] - X[0][2] * X[1][1];
            float c21 = X[0][2] * X[1][0] - X[0][0] * X[1][2];
            float c22 = X[0][0] * X[1][1] - X[0][1] * X[1][0];
            float d = X[0][0] * c00 + X[0][1] * c01 + X[0][2] * c02;
            float id = 0.5f / d;
            X[0][0] = 0.5f * X[0][0] + id * c00;  X[0][1] = 0.5f * X[0][1] + id * c01;
            X[0][2] = 0.5f * X[0][2] + id * c02;  X[1][0] = 0.5f * X[1][0] + id * c10;
            X[1][1] = 0.5f * X[1][1] + id * c11;  X[1][2] = 0.5f * X[1][2] + id * c12;
            X[2][0] = 0.5f * X[2][0] + id * c20;  X[2][1] = 0.5f * X[2][1] + id * c21;
            X[2][2] = 0.5f * X[2][2] + id * c22;
        }
#pragma unroll
        for (int i = 0; i < 9; ++i)
            *reinterpret_cast<float*>(smem + RBUF + tid * 36 + i * 4) = X[i / 3][i % 3];

        float x0[32];
        x0[0] = s1 - 1.0f;  x0[1] = s2 - 1.0f;  x0[2] = s3 - 1.0f;
#pragma unroll
        for (int i = 0; i < 3; ++i)
#pragma unroll
            for (int j = 0; j < 3; ++j)
                x0[3 + i * 3 + j] = G[i][j] - ((i == j) ? 1.0f : 0.0f);
        x0[12] = detF - 1.0f;
        x0[13] = logf(detF) - 1.0f;
        float f00 = fmaxf(Fm[0][0], 1e-6f);
        x0[14] = f00 - 1.0f;
        x0[15] = logf(f00) - 1.0f;
#pragma unroll
        for (int k = 0; k < 9; ++k) x0[16 + k] = C[(size_t)p * 9 + k];
#pragma unroll
        for (int k = 25; k < 32; ++k) x0[k] = 0.0f;

#pragma unroll
        for (int cp = 0; cp < 16; ++cp) {
            float v0 = x0[2 * cp], v1 = x0[2 * cp + 1];
            __nv_bfloat162 h = __floats2bfloat162_rn(v0, v1);
            float l0 = v0 - __bfloat162float(__low2bfloat16(h));
            float l1 = v1 - __bfloat162float(__high2bfloat16(h));
            __nv_bfloat162 lo = __floats2bfloat162_rn(l0, l1);
            *reinterpret_cast<uint32_t*>(smem + ACT_H + tid * 528 + cp * 4) =
                *reinterpret_cast<uint32_t*>(&h);
            *reinterpret_cast<uint32_t*>(smem + ACT_L + tid * 528 + cp * 4) =
                *reinterpret_cast<uint32_t*>(&lo);
        }
    }

    // --- mainloop: 25 global chunks = L1(1) + L2..L4(8 each) ---------------
    float acc[4][8][4];
#pragma unroll
    for (int mt = 0; mt < 4; ++mt)
#pragma unroll
        for (int n8 = 0; n8 < 8; ++n8)
#pragma unroll
            for (int r = 0; r < 4; ++r) acc[mt][n8][r] = 0.0f;

    const uint32_t a_off = (uint32_t)(rm + (lane & 15)) * 528u + ((lane >> 4) << 4);
    const uint32_t w_off =
        (uint32_t)(cn + ((lane >> 4) << 3) + (lane & 7)) * 80u + (((lane >> 3) & 1) << 4);

    uint32_t stg = 0;
#pragma unroll 1
    for (int gi = 0; gi < 25; ++gi) {
        if (gi + 1 < 25) {
            int l2 = (gi >> 3) + 1;
            int c2 = gi & 7;
            loadW(g_wtH + (l2 - 1) * 65536, g_wtL + (l2 - 1) * 65536, 256, c2, stg ^ 1);
            CP_WAIT(1);
        } else {
            CP_WAIT(0);
        }
        __syncthreads();

        const int ch = (gi == 0) ? 0 : ((gi - 1) & 7);
        const uint32_t acol = (uint32_t)ch * 64u;
        const uint32_t sW = sb + WSTG + stg * STAGE_SZ;

#pragma unroll
        for (int ks = 0; ks < 2; ++ks) {
            uint32_t ah[4][4], al[4][4], bw[8][2];
#pragma unroll
            for (int mt = 0; mt < 4; ++mt) {
                LDSM4(ah[mt], sb + ACT_H + a_off + mt * 8448 + acol + ks * 32);
                LDSM4(al[mt], sb + ACT_L + a_off + mt * 8448 + acol + ks * 32);
            }
#pragma unroll
            for (int ng = 0; ng < 4; ++ng) {
                uint32_t r4[4];
                LDSM4(r4, sW + w_off + ng * 1280 + ks * 32);
                bw[2 * ng][0] = r4[0]; bw[2 * ng][1] = r4[1];
                bw[2 * ng + 1][0] = r4[2]; bw[2 * ng + 1][1] = r4[3];
            }
#pragma unroll
            for (int mt = 0; mt < 4; ++mt)
#pragma unroll
                for (int n8 = 0; n8 < 8; ++n8) MMA_BF16(acc[mt][n8], ah[mt], bw[n8]);
#pragma unroll
            for (int mt = 0; mt < 4; ++mt)
#pragma unroll
                for (int n8 = 0; n8 < 8; ++n8) MMA_BF16(acc[mt][n8], al[mt], bw[n8]);
#pragma unroll
            for (int ng = 0; ng < 4; ++ng) {
                uint32_t r4[4];
                LDSM4(r4, sW + 20480 + w_off + ng * 1280 + ks * 32);
                bw[2 * ng][0] = r4[0]; bw[2 * ng][1] = r4[1];
                bw[2 * ng + 1][0] = r4[2]; bw[2 * ng + 1][1] = r4[3];
            }
#pragma unroll
            for (int mt = 0; mt < 4; ++mt)
#pragma unroll
                for (int n8 = 0; n8 < 8; ++n8) MMA_BF16(acc[mt][n8], ah[mt], bw[n8]);
        }
        __syncthreads();
        stg ^= 1;

        // --- layer boundary: GELU + split + write new act into SMEM --------
        const bool eol = (gi == 0) || (((gi - 1) & 7) == 7);
        if (eol) {
            const int l = (gi == 0) ? 0 : (((gi - 1) >> 3) + 1);
            const int r_l = lane >> 2, c_l = (lane & 3) << 1;
#pragma unroll
            for (int mt = 0; mt < 4; ++mt)
#pragma unroll
                for (int n8 = 0; n8 < 8; ++n8) {
                    int row = rm + mt * 16 + r_l;
                    int col = cn + n8 * 8 + c_l;
                    float* a4 = acc[mt][n8];
                    float b0 = *reinterpret_cast<float*>(smem + BIAS_OFF + col * 4);
                    float b1v = *reinterpret_cast<float*>(smem + BIAS_OFF + (col + 1) * 4);
                    float g0 = gelu_f(a4[0] + b0);
                    float g1 = gelu_f(a4[1] + b1v);
                    float g2 = gelu_f(a4[2] + b0);
                    float g3 = gelu_f(a4[3] + b1v);
                    __nv_bfloat162 h01 = __floats2bfloat162_rn(g0, g1);
                    __nv_bfloat162 h23 = __floats2bfloat162_rn(g2, g3);
                    float l0 = g0 - __bfloat162float(__low2bfloat16(h01));
                    float l1 = g1 - __bfloat162float(__high2bfloat16(h01));
                    float l2 = g2 - __bfloat162float(__low2bfloat16(h23));
                    float l3 = g3 - __bfloat162float(__high2bfloat16(h23));
                    __nv_bfloat162 q01 = __floats2bfloat162_rn(l0, l1);
                    __nv_bfloat162 q23 = __floats2bfloat162_rn(l2, l3);
                    *reinterpret_cast<uint32_t*>(smem + ACT_H + row * 528 + col * 2) =
                        *reinterpret_cast<uint32_t*>(&h01);
                    *reinterpret_cast<uint32_t*>(smem + ACT_H + (row + 8) * 528 + col * 2) =
                        *reinterpret_cast<uint32_t*>(&h23);
                    *reinterpret_cast<uint32_t*>(smem + ACT_L + row * 528 + col * 2) =
                        *reinterpret_cast<uint32_t*>(&q01);
                    *reinterpret_cast<uint32_t*>(smem + ACT_L + (row + 8) * 528 + col * 2) =
                        *reinterpret_cast<uint32_t*>(&q23);
                    a4[0] = a4[1] = a4[2] = a4[3] = 0.0f;
                }
            __syncthreads();
            if (l < 3) {
                const float* nb = (l == 0) ? b2 : ((l == 1) ? b3 : b4);
                *reinterpret_cast<float*>(smem + BIAS_OFF + tid * 4) = nb[tid];
            }
        }
    }

    // --- final layer: 256 -> 9 + symmetrize + P=R@x, cauchy = P@F^T --------
    for (int i = tid; i < 2304; i += 256)
        *reinterpret_cast<float*>(smem + W5S + i * 4) = W5[i];
    if (tid < 9)
        *reinterpret_cast<float*>(smem + B5S + tid * 4) = b5[tid];
    __syncthreads();

#pragma unroll 1
    for (int rr = 0; rr < 16; ++rr) {
        int row = warp * 16 + rr;
        float s[9];
#pragma unroll
        for (int j = 0; j < 9; ++j) s[j] = 0.0f;
#pragma unroll
        for (int t4 = 0; t4 < 4; ++t4) {
            int cp = lane + 32 * t4;
            uint32_t hp = *reinterpret_cast<uint32_t*>(smem + ACT_H + row * 528 + cp * 4);
            uint32_t lp = *reinterpret_cast<uint32_t*>(smem + ACT_L + row * 528 + cp * 4);
            __nv_bfloat162 h = *reinterpret_cast<__nv_bfloat162*>(&hp);
            __nv_bfloat162 lo = *reinterpret_cast<__nv_bfloat162*>(&lp);
            float x0 = __bfloat162float(__low2bfloat16(h)) + __bfloat162float(__low2bfloat16(lo));
            float x1 = __bfloat162float(__high2bfloat16(h)) + __bfloat162float(__high2bfloat16(lo));
            const float* w0 = reinterpret_cast<const float*>(smem + W5S) + (2 * cp) * 9;
#pragma unroll
            for (int j = 0; j < 9; ++j) s[j] += x0 * w0[j] + x1 * w0[9 + j];
        }
#pragma unroll
        for (int j = 0; j < 9; ++j) {
#pragma unroll
            for (int o = 16; o >= 1; o >>= 1)
                s[j] += __shfl_xor_sync(0xffffffffu, s[j], o);
        }
        if (lane == 0) {
            int p = tile * 128 + row;
            float x[3][3], xs[3][3], Rm[3][3], Fm[3][3], P[3][3];
#pragma unroll
            for (int i = 0; i < 3; ++i)
#pragma unroll
                for (int j = 0; j < 3; ++j) {
                    x[i][j] = s[i * 3 + j] +
                              *reinterpret_cast<float*>(smem + B5S + (i * 3 + j) * 4);
                    Rm[i][j] = *reinterpret_cast<float*>(smem + RBUF + row * 36 + (i * 3 + j) * 4);
                    Fm[i][j] = F[(size_t)p * 9 + i * 3 + j];
                }
#pragma unroll
            for (int i = 0; i < 3; ++i)
#pragma unroll
                for (int j = 0; j < 3; ++j) xs[i][j] = 0.5f * (x[i][j] + x[j][i]);
#pragma unroll
            for (int i = 0; i < 3; ++i)
#pragma unroll
                for (int j = 0; j < 3; ++j)
                    P[i][j] = Rm[i][0] * xs[0][j] + Rm[i][1] * xs[1][j] + Rm[i][2] * xs[2][j];
#pragma unroll
            for (int i = 0; i < 3; ++i)
#pragma unroll
                for (int j = 0; j < 3; ++j)
                    out[(size_t)p * 9 + i * 3 + j] =
                        P[i][0] * Fm[j][0] + P[i][1] * Fm[j][1] + P[i][2] * Fm[j][2];
        }
    }
}

// ---------------------------------------------------------------------------
extern "C" void kernel_launch(void* const* d_in, const int* in_sizes, int n_in,
                              void* d_out, int out_size) {
    const float* F    = (const float*)d_in[0];
    const float* C    = (const float*)d_in[1];
    const float* emb  = (const float*)d_in[2];
    const int*   traj = (const int*)d_in[3];
    const float* W1   = (const float*)d_in[4];
    const float* b1   = (const float*)d_in[5];
    const float* W2   = (const float*)d_in[6];
    const float* b2   = (const float*)d_in[7];
    const float* W3   = (const float*)d_in[8];
    const float* b3   = (const float*)d_in[9];
    const float* W4   = (const float*)d_in[10];
    const float* b4   = (const float*)d_in[11];
    const float* W5   = (const float*)d_in[12];
    const float* b5   = (const float*)d_in[13];
    float* out = (float*)d_out;

    int B = in_sizes[0] / 9;
    if (B > MAXB) B = MAXB;

    static bool attr_set = false;
    if (!attr_set) {
        cudaFuncSetAttribute(fused_kernel,
                             cudaFuncAttributeMaxDynamicSharedMemorySize, SMEM_TOT);
        attr_set = true;
    }

    prep_all_kernel<<<801, 256>>>(emb, traj, W1, b1, W2, W3, W4);
    fused_kernel<<<B / 128, 256, SMEM_TOT>>>(F, C, b2, b3, b4, W5, b5, out);
}

// round 7
// speedup vs baseline: 2.8602x; 1.1626x over previous
#include <cuda_runtime.h>
#include <cuda_bf16.h>
#include <math.h>
#include <math_constants.h>
#include <stdint.h>

// ============================================================================
// StressNNEval — round 7: fused kernel, weights pre-packed in mma-fragment
// order and loaded via LDG.128 from L2 (no cp.async, no W-smem, no W-ldmatrix).
// Warp tile 128M x 32N: per-warp private weights, read-only ACT smem within a
// layer -> no intra-layer barriers. bf16x3 split precision unchanged.
// ============================================================================

#define MAXB 262144
#define HID  256

__device__ __align__(128) float    g_b1p[HID];
__device__ __align__(128) uint32_t g_f1[16384];        // L1 frags (hi+lo)
__device__ __align__(128) uint32_t g_fN[3 * 65536];    // L2..L4 frags (hi+lo)

// ---- smem layout (dynamic, 150080 B) --------------------------------------
#define ACT_H    0              // 128 rows x 528B (256 bf16 + 16 pad)
#define ACT_L    67584
#define BIAS_OFF 135168         // 256 fp32
#define RBUF     136192         // 128 x 9 fp32
#define W5S      140800         // 256x9 fp32
#define B5S      150016
#define SMEM_TOT 150080

// ---------------------------------------------------------------------------
__device__ __forceinline__ uint32_t smem_u32(const void* p) {
    uint32_t a;
    asm("{ .reg .u64 t; cvta.to.shared.u64 t, %1; cvt.u32.u64 %0, t; }"
        : "=r"(a) : "l"(p));
    return a;
}
#define LDSM4(r, addr)                                                        \
    asm volatile("ldmatrix.sync.aligned.m8n8.x4.shared.b16 {%0,%1,%2,%3}, [%4];" \
        : "=r"((r)[0]), "=r"((r)[1]), "=r"((r)[2]), "=r"((r)[3]) : "r"(addr))

#define MMA_BF16(c, a, b0, b1)                                                \
    asm volatile("mma.sync.aligned.m16n8k16.row.col.f32.bf16.bf16.f32 "       \
        "{%0,%1,%2,%3}, {%4,%5,%6,%7}, {%8,%9}, {%0,%1,%2,%3};"               \
        : "+f"((c)[0]), "+f"((c)[1]), "+f"((c)[2]), "+f"((c)[3])              \
        : "r"((a)[0]), "r"((a)[1]), "r"((a)[2]), "r"((a)[3]),                 \
          "r"(b0), "r"(b1))

__device__ __forceinline__ float gelu_f(float t) {
    return 0.5f * t * (1.0f + erff(t * 0.7071067811865475f));
}

// ---------------------------------------------------------------------------
// prep: block 0 folds latent into b1; blocks 1..64: L1 frags;
//       blocks 65..832: L2..L4 frags.
// Fragment uint32 index decomposition (per layer):
//   lane4=idx&3, lane=(idx>>2)&31, g=(idx>>7)&7, warp=(idx>>10)&7, c=(idx>>13)&7
//   half=g>>2 (0 hi, 1 lo), ks=(g>>1)&1, npair=g&1
//   n8 = npair*2 + (lane4>>1), r = lane4&1
//   n = warp*32 + n8*8 + lane/4 ;  k = c*32 + ks*16 + (lane%4)*2 + r*8
//   value = pack(bf16part(W[k][n]), bf16part(W[k+1][n]))
// ---------------------------------------------------------------------------
__global__ void prep_all_kernel(const float* __restrict__ emb,
                                const int* __restrict__ traj,
                                const float* __restrict__ W1,
                                const float* __restrict__ b1,
                                const float* __restrict__ W2,
                                const float* __restrict__ W3,
                                const float* __restrict__ W4) {
    int bid = blockIdx.x, tid = threadIdx.x;
    if (bid == 0) {
        int t = traj[0];
        const float* e = emb + (size_t)t * 128;
        float s = b1[tid];
#pragma unroll 4
        for (int k = 0; k < 128; ++k)
            s += e[k] * W1[(size_t)(25 + k) * HID + tid];
        g_b1p[tid] = s;
        return;
    }
    bool isL1 = (bid <= 64);
    int idx = isL1 ? (bid - 1) * 256 + tid : 0;
    int L = 0;
    if (!isL1) {
        int q = (bid - 65) * 256 + tid;        // 0..196607
        L = q >> 16;
        idx = q & 65535;
    }
    int lane4 = idx & 3;
    int lane  = (idx >> 2) & 31;
    int g     = (idx >> 7) & 7;
    int warp  = (idx >> 10) & 7;
    int c     = isL1 ? 0 : ((idx >> 13) & 7);
    int half  = g >> 2;
    int ks    = (g >> 1) & 1;
    int npair = g & 1;
    int n8    = npair * 2 + (lane4 >> 1);
    int r     = lane4 & 1;
    int n = warp * 32 + n8 * 8 + (lane >> 2);
    int k = c * 32 + ks * 16 + (lane & 3) * 2 + r * 8;

    float w0, w1;
    if (isL1) {
        w0 = (k < 25)     ? W1[(size_t)k * HID + n]       : 0.0f;
        w1 = (k + 1 < 25) ? W1[(size_t)(k + 1) * HID + n] : 0.0f;
    } else {
        const float* W = (L == 0) ? W2 : ((L == 1) ? W3 : W4);
        w0 = W[(size_t)k * HID + n];
        w1 = W[(size_t)(k + 1) * HID + n];
    }
    __nv_bfloat16 h0 = __float2bfloat16_rn(w0);
    __nv_bfloat16 h1 = __float2bfloat16_rn(w1);
    uint32_t val;
    if (half == 0) {
        val = (uint32_t)*reinterpret_cast<uint16_t*>(&h0) |
              ((uint32_t)*reinterpret_cast<uint16_t*>(&h1) << 16);
    } else {
        __nv_bfloat16 l0 = __float2bfloat16_rn(w0 - __bfloat162float(h0));
        __nv_bfloat16 l1 = __float2bfloat16_rn(w1 - __bfloat162float(h1));
        val = (uint32_t)*reinterpret_cast<uint16_t*>(&l0) |
              ((uint32_t)*reinterpret_cast<uint16_t*>(&l1) << 16);
    }
    if (isL1) g_f1[idx] = val;
    else      g_fN[(size_t)L * 65536 + idx] = val;
}

// ---------------------------------------------------------------------------
// Fused kernel: 256 threads, 8 warps, warp tile 128M x 32N.
// ---------------------------------------------------------------------------
__global__ __launch_bounds__(256, 1)
void fused_kernel(const float* __restrict__ F, const float* __restrict__ C,
                  const float* __restrict__ b2, const float* __restrict__ b3,
                  const float* __restrict__ b4, const float* __restrict__ W5,
                  const float* __restrict__ b5, float* __restrict__ out) {
    extern __shared__ char smem[];
    const uint32_t sb = smem_u32(smem);
    const int tid = threadIdx.x, lane = tid & 31, warp = tid >> 5;
    const int tile = blockIdx.x;

    *reinterpret_cast<float*>(smem + BIAS_OFF + tid * 4) = g_b1p[tid];

    // --- in-kernel prep: invariants + polar rotation -> X0 into ACT, R -> RBUF
    if (tid < 128) {
        int p = tile * 128 + tid;
        float Fm[3][3];
#pragma unroll
        for (int i = 0; i < 3; ++i)
#pragma unroll
            for (int j = 0; j < 3; ++j)
                Fm[i][j] = F[(size_t)p * 9 + i * 3 + j];

        float G[3][3];
#pragma unroll
        for (int i = 0; i < 3; ++i)
#pragma unroll
            for (int j = 0; j < 3; ++j)
                G[i][j] = Fm[0][i] * Fm[0][j] + Fm[1][i] * Fm[1][j] + Fm[2][i] * Fm[2][j];

        float q = (G[0][0] + G[1][1] + G[2][2]) * (1.0f / 3.0f);
        float p1 = G[0][1] * G[0][1] + G[0][2] * G[0][2] + G[1][2] * G[1][2];
        float p2 = (G[0][0] - q) * (G[0][0] - q) + (G[1][1] - q) * (G[1][1] - q) +
                   (G[2][2] - q) * (G[2][2] - q) + 2.0f * p1;
        float e1, e2, e3;
        float pp = sqrtf(p2 * (1.0f / 6.0f));
        if (pp < 1e-20f) {
            e1 = e2 = e3 = q;
        } else {
            float ip = 1.0f / pp;
            float b00 = (G[0][0] - q) * ip, b11 = (G[1][1] - q) * ip, b22 = (G[2][2] - q) * ip;
            float b01 = G[0][1] * ip, b02 = G[0][2] * ip, b12 = G[1][2] * ip;
            float detB = b00 * (b11 * b22 - b12 * b12) - b01 * (b01 * b22 - b12 * b02) +
                         b02 * (b01 * b12 - b11 * b02);
            float r = fminf(1.0f, fmaxf(-1.0f, detB * 0.5f));
            float phi = acosf(r) * (1.0f / 3.0f);
            e1 = q + 2.0f * pp * cosf(phi);
            e3 = q + 2.0f * pp * cosf(phi + 2.0943951023931953f);
            e2 = 3.0f * q - e1 - e3;
        }
        float s1 = sqrtf(fmaxf(e1, 0.0f));
        float s2 = sqrtf(fmaxf(e2, 0.0f));
        float s3 = sqrtf(fmaxf(e3, 0.0f));

        float detF = Fm[0][0] * (Fm[1][1] * Fm[2][2] - Fm[1][2] * Fm[2][1]) -
                     Fm[0][1] * (Fm[1][0] * Fm[2][2] - Fm[1][2] * Fm[2][0]) +
                     Fm[0][2] * (Fm[1][0] * Fm[2][1] - Fm[1][1] * Fm[2][0]);

        float X[3][3];
#pragma unroll
        for (int i = 0; i < 3; ++i)
#pragma unroll
            for (int j = 0; j < 3; ++j) X[i][j] = Fm[i][j];
#pragma unroll
        for (int it = 0; it < 8; ++it) {
            float c00 = X[1][1] * X[2][2] - X[1][2] * X[2][1];
            float c01 = X[1][2] * X[2][0] - X[1][0] * X[2][2];
            float c02 = X[1][0] * X[2][1] - X[1][1] * X[2][0];
            float c10 = X[0][2] * X[2][1] - X[0][1] * X[2][2];
            float c11 = X[0][0] * X[2][2] - X[0][2] * X[2][0];
            float c12 = X[0][1] * X[2][0] - X[0][0] * X[2][1];
            float c20 = X[0][1] * X[1][2] - X[0][2] * X[1][1];
            float c21 = X[0][2] * X[1][0] - X[0][0] * X[1][2];
            float c22 = X[0][0] * X[1][1] - X[0][1] * X[1][0];
            float d = X[0][0] * c00 + X[0][1] * c01 + X[0][2] * c02;
            float id = 0.5f / d;
            X[0][0] = 0.5f * X[0][0] + id * c00;  X[0][1] = 0.5f * X[0][1] + id * c01;
            X[0][2] = 0.5f * X[0][2] + id * c02;  X[1][0] = 0.5f * X[1][0] + id * c10;
            X[1][1] = 0.5f * X[1][1] + id * c11;  X[1][2] = 0.5f * X[1][2] + id * c12;
            X[2][0] = 0.5f * X[2][0] + id * c20;  X[2][1] = 0.5f * X[2][1] + id * c21;
            X[2][2] = 0.5f * X[2][2] + id * c22;
        }
#pragma unroll
        for (int i = 0; i < 9; ++i)
            *reinterpret_cast<float*>(smem + RBUF + tid * 36 + i * 4) = X[i / 3][i % 3];

        float x0[32];
        x0[0] = s1 - 1.0f;  x0[1] = s2 - 1.0f;  x0[2] = s3 - 1.0f;
#pragma unroll
        for (int i = 0; i < 3; ++i)
#pragma unroll
            for (int j = 0; j < 3; ++j)
                x0[3 + i * 3 + j] = G[i][j] - ((i == j) ? 1.0f : 0.0f);
        x0[12] = detF - 1.0f;
        x0[13] = logf(detF) - 1.0f;
        float f00 = fmaxf(Fm[0][0], 1e-6f);
        x0[14] = f00 - 1.0f;
        x0[15] = logf(f00) - 1.0f;
#pragma unroll
        for (int k = 0; k < 9; ++k) x0[16 + k] = C[(size_t)p * 9 + k];
#pragma unroll
        for (int k = 25; k < 32; ++k) x0[k] = 0.0f;

#pragma unroll
        for (int cp = 0; cp < 16; ++cp) {
            float v0 = x0[2 * cp], v1 = x0[2 * cp + 1];
            __nv_bfloat162 h = __floats2bfloat162_rn(v0, v1);
            float l0 = v0 - __bfloat162float(__low2bfloat16(h));
            float l1 = v1 - __bfloat162float(__high2bfloat16(h));
            __nv_bfloat162 lo = __floats2bfloat162_rn(l0, l1);
            *reinterpret_cast<uint32_t*>(smem + ACT_H + tid * 528 + cp * 4) =
                *reinterpret_cast<uint32_t*>(&h);
            *reinterpret_cast<uint32_t*>(smem + ACT_L + tid * 528 + cp * 4) =
                *reinterpret_cast<uint32_t*>(&lo);
        }
    }
    __syncthreads();

    // --- mainloop: 25 chunks = L1(1) + L2..L4(8 each); no intra-layer syncs
    float acc[8][4][4];
#pragma unroll
    for (int mt = 0; mt < 8; ++mt)
#pragma unroll
        for (int n8 = 0; n8 < 4; ++n8)
#pragma unroll
            for (int r = 0; r < 4; ++r) acc[mt][n8][r] = 0.0f;

    const uint32_t a_off = (uint32_t)(lane & 15) * 528u + ((lane >> 4) << 4);

#pragma unroll 1
    for (int gi = 0; gi < 25; ++gi) {
        const int l  = (gi == 0) ? 0 : (((gi - 1) >> 3) + 1);
        const int ch = (gi == 0) ? 0 : ((gi - 1) & 7);
        const uint4* wbase = (l == 0)
            ? reinterpret_cast<const uint4*>(g_f1)
            : reinterpret_cast<const uint4*>(g_fN + (size_t)(l - 1) * 65536);
        const int fb = ((ch * 8 + warp) * 8) * 32 + lane;

        uint4 wfh[4], wfl[4];
#pragma unroll
        for (int g = 0; g < 4; ++g) {
            wfh[g] = __ldg(wbase + fb + g * 32);
            wfl[g] = __ldg(wbase + fb + (g + 4) * 32);
        }

        const uint32_t acol = (uint32_t)ch * 64u;
#pragma unroll
        for (int ks = 0; ks < 2; ++ks) {
            uint32_t bh[4][2], bl[4][2];
            {
                uint4 q0 = wfh[ks * 2], q1 = wfh[ks * 2 + 1];
                bh[0][0] = q0.x; bh[0][1] = q0.y; bh[1][0] = q0.z; bh[1][1] = q0.w;
                bh[2][0] = q1.x; bh[2][1] = q1.y; bh[3][0] = q1.z; bh[3][1] = q1.w;
                uint4 p0 = wfl[ks * 2], p1 = wfl[ks * 2 + 1];
                bl[0][0] = p0.x; bl[0][1] = p0.y; bl[1][0] = p0.z; bl[1][1] = p0.w;
                bl[2][0] = p1.x; bl[2][1] = p1.y; bl[3][0] = p1.z; bl[3][1] = p1.w;
            }
            uint32_t ah[8][4], al[8][4];
#pragma unroll
            for (int mt = 0; mt < 8; ++mt)
                LDSM4(ah[mt], sb + ACT_H + a_off + mt * 8448 + acol + ks * 32);
#pragma unroll
            for (int mt = 0; mt < 8; ++mt)
#pragma unroll
                for (int n8 = 0; n8 < 4; ++n8)
                    MMA_BF16(acc[mt][n8], ah[mt], bh[n8][0], bh[n8][1]);
#pragma unroll
            for (int mt = 0; mt < 8; ++mt)
                LDSM4(al[mt], sb + ACT_L + a_off + mt * 8448 + acol + ks * 32);
#pragma unroll
            for (int mt = 0; mt < 8; ++mt)
#pragma unroll
                for (int n8 = 0; n8 < 4; ++n8)
                    MMA_BF16(acc[mt][n8], al[mt], bh[n8][0], bh[n8][1]);
#pragma unroll
            for (int mt = 0; mt < 8; ++mt)
#pragma unroll
                for (int n8 = 0; n8 < 4; ++n8)
                    MMA_BF16(acc[mt][n8], ah[mt], bl[n8][0], bl[n8][1]);
        }

        // --- layer boundary: GELU + split + write new act into SMEM --------
        const bool eol = (gi == 0) || (((gi - 1) & 7) == 7);
        if (eol) {
            __syncthreads();                   // all reads of old acts done
            const int r_l = lane >> 2, c_l = (lane & 3) << 1;
#pragma unroll
            for (int mt = 0; mt < 8; ++mt)
#pragma unroll
                for (int n8 = 0; n8 < 4; ++n8) {
                    int row = mt * 16 + r_l;
                    int col = warp * 32 + n8 * 8 + c_l;
                    float* a4 = acc[mt][n8];
                    float b0 = *reinterpret_cast<float*>(smem + BIAS_OFF + col * 4);
                    float b1v = *reinterpret_cast<float*>(smem + BIAS_OFF + (col + 1) * 4);
                    float g0 = gelu_f(a4[0] + b0);
                    float g1 = gelu_f(a4[1] + b1v);
                    float g2 = gelu_f(a4[2] + b0);
                    float g3 = gelu_f(a4[3] + b1v);
                    __nv_bfloat162 h01 = __floats2bfloat162_rn(g0, g1);
                    __nv_bfloat162 h23 = __floats2bfloat162_rn(g2, g3);
                    float l0 = g0 - __bfloat162float(__low2bfloat16(h01));
                    float l1 = g1 - __bfloat162float(__high2bfloat16(h01));
                    float l2 = g2 - __bfloat162float(__low2bfloat16(h23));
                    float l3 = g3 - __bfloat162float(__high2bfloat16(h23));
                    __nv_bfloat162 q01 = __floats2bfloat162_rn(l0, l1);
                    __nv_bfloat162 q23 = __floats2bfloat162_rn(l2, l3);
                    *reinterpret_cast<uint32_t*>(smem + ACT_H + row * 528 + col * 2) =
                        *reinterpret_cast<uint32_t*>(&h01);
                    *reinterpret_cast<uint32_t*>(smem + ACT_H + (row + 8) * 528 + col * 2) =
                        *reinterpret_cast<uint32_t*>(&h23);
                    *reinterpret_cast<uint32_t*>(smem + ACT_L + row * 528 + col * 2) =
                        *reinterpret_cast<uint32_t*>(&q01);
                    *reinterpret_cast<uint32_t*>(smem + ACT_L + (row + 8) * 528 + col * 2) =
                        *reinterpret_cast<uint32_t*>(&q23);
                    a4[0] = a4[1] = a4[2] = a4[3] = 0.0f;
                }
            if (l < 3) {
                const float* nb = (l == 0) ? b2 : ((l == 1) ? b3 : b4);
                *reinterpret_cast<float*>(smem + BIAS_OFF + tid * 4) = nb[tid];
            }
            __syncthreads();                   // new acts visible
        }
    }

    // --- final layer: 256 -> 9 + symmetrize + P=R@x, cauchy = P@F^T --------
    for (int i = tid; i < 2304; i += 256)
        *reinterpret_cast<float*>(smem + W5S + i * 4) = W5[i];
    if (tid < 9)
        *reinterpret_cast<float*>(smem + B5S + tid * 4) = b5[tid];
    __syncthreads();

#pragma unroll 1
    for (int rr = 0; rr < 16; ++rr) {
        int row = warp * 16 + rr;
        float s[9];
#pragma unroll
        for (int j = 0; j < 9; ++j) s[j] = 0.0f;
#pragma unroll
        for (int t4 = 0; t4 < 4; ++t4) {
            int cp = lane + 32 * t4;
            uint32_t hp = *reinterpret_cast<uint32_t*>(smem + ACT_H + row * 528 + cp * 4);
            uint32_t lp = *reinterpret_cast<uint32_t*>(smem + ACT_L + row * 528 + cp * 4);
            __nv_bfloat162 h = *reinterpret_cast<__nv_bfloat162*>(&hp);
            __nv_bfloat162 lo = *reinterpret_cast<__nv_bfloat162*>(&lp);
            float x0 = __bfloat162float(__low2bfloat16(h)) + __bfloat162float(__low2bfloat16(lo));
            float x1 = __bfloat162float(__high2bfloat16(h)) + __bfloat162float(__high2bfloat16(lo));
            const float* w0 = reinterpret_cast<const float*>(smem + W5S) + (2 * cp) * 9;
#pragma unroll
            for (int j = 0; j < 9; ++j) s[j] += x0 * w0[j] + x1 * w0[9 + j];
        }
#pragma unroll
        for (int j = 0; j < 9; ++j) {
#pragma unroll
            for (int o = 16; o >= 1; o >>= 1)
                s[j] += __shfl_xor_sync(0xffffffffu, s[j], o);
        }
        if (lane == 0) {
            int p = tile * 128 + row;
            float x[3][3], xs[3][3], Rm[3][3], Fm[3][3], P[3][3];
#pragma unroll
            for (int i = 0; i < 3; ++i)
#pragma unroll
                for (int j = 0; j < 3; ++j) {
                    x[i][j] = s[i * 3 + j] +
                              *reinterpret_cast<float*>(smem + B5S + (i * 3 + j) * 4);
                    Rm[i][j] = *reinterpret_cast<float*>(smem + RBUF + row * 36 + (i * 3 + j) * 4);
                    Fm[i][j] = F[(size_t)p * 9 + i * 3 + j];
                }
#pragma unroll
            for (int i = 0; i < 3; ++i)
#pragma unroll
                for (int j = 0; j < 3; ++j) xs[i][j] = 0.5f * (x[i][j] + x[j][i]);
#pragma unroll
            for (int i = 0; i < 3; ++i)
#pragma unroll
                for (int j = 0; j < 3; ++j)
                    P[i][j] = Rm[i][0] * xs[0][j] + Rm[i][1] * xs[1][j] + Rm[i][2] * xs[2][j];
#pragma unroll
            for (int i = 0; i < 3; ++i)
#pragma unroll
                for (int j = 0; j < 3; ++j)
                    out[(size_t)p * 9 + i * 3 + j] =
                        P[i][0] * Fm[j][0] + P[i][1] * Fm[j][1] + P[i][2] * Fm[j][2];
        }
    }
}

// ---------------------------------------------------------------------------
extern "C" void kernel_launch(void* const* d_in, const int* in_sizes, int n_in,
                              void* d_out, int out_size) {
    const float* F    = (const float*)d_in[0];
    const float* C    = (const float*)d_in[1];
    const float* emb  = (const float*)d_in[2];
    const int*   traj = (const int*)d_in[3];
    const float* W1   = (const float*)d_in[4];
    const float* b1   = (const float*)d_in[5];
    const float* W2   = (const float*)d_in[6];
    const float* b2   = (const float*)d_in[7];
    const float* W3   = (const float*)d_in[8];
    const float* b3   = (const float*)d_in[9];
    const float* W4   = (const float*)d_in[10];
    const float* b4   = (const float*)d_in[11];
    const float* W5   = (const float*)d_in[12];
    const float* b5   = (const float*)d_in[13];
    float* out = (float*)d_out;

    int B = in_sizes[0] / 9;
    if (B > MAXB) B = MAXB;

    static bool attr_set = false;
    if (!attr_set) {
        cudaFuncSetAttribute(fused_kernel,
                             cudaFuncAttributeMaxDynamicSharedMemorySize, SMEM_TOT);
        attr_set = true;
    }

    prep_all_kernel<<<833, 256>>>(emb, traj, W1, b1, W2, W3, W4);
    fused_kernel<<<B / 128, 256, SMEM_TOT>>>(F, C, b2, b3, b4, W5, b5, out);
}

// round 8
// speedup vs baseline: 3.1991x; 1.1185x over previous
#include <cuda_runtime.h>
#include <cuda_bf16.h>
#include <math.h>
#include <math_constants.h>
#include <stdint.h>

// ============================================================================
// StressNNEval — round 8: 64-row tiles, 2 CTAs/SM (4 warps/SMSP), interleaved
// LDSM/MMA to fit 128 regs. Weights stay in pre-packed mma-fragment order,
// loaded by LDG.128 from L2. bf16x3 split precision unchanged.
// ============================================================================

#define MAXB 262144
#define HID  256

__device__ __align__(128) float    g_b1p[HID];
__device__ __align__(128) uint32_t g_f1[16384];        // L1 frags (hi+lo)
__device__ __align__(128) uint32_t g_fN[3 * 65536];    // L2..L4 frags (hi+lo)

// ---- smem layout (dynamic, 80192 B; 2 CTAs/SM) -----------------------------
#define ACT_H    0              // 64 rows x 528B
#define ACT_L    33792
#define BIAS_OFF 67584          // 256 fp32
#define RBUF     68608          // 64 x 9 fp32
#define W5S      70912          // 256x9 fp32
#define B5S      80128
#define SMEM_TOT 80192

// ---------------------------------------------------------------------------
__device__ __forceinline__ uint32_t smem_u32(const void* p) {
    uint32_t a;
    asm("{ .reg .u64 t; cvta.to.shared.u64 t, %1; cvt.u32.u64 %0, t; }"
        : "=r"(a) : "l"(p));
    return a;
}
#define LDSM4(r, addr)                                                        \
    asm volatile("ldmatrix.sync.aligned.m8n8.x4.shared.b16 {%0,%1,%2,%3}, [%4];" \
        : "=r"((r)[0]), "=r"((r)[1]), "=r"((r)[2]), "=r"((r)[3]) : "r"(addr))

#define MMA_BF16(c, a, b0, b1)                                                \
    asm volatile("mma.sync.aligned.m16n8k16.row.col.f32.bf16.bf16.f32 "       \
        "{%0,%1,%2,%3}, {%4,%5,%6,%7}, {%8,%9}, {%0,%1,%2,%3};"               \
        : "+f"((c)[0]), "+f"((c)[1]), "+f"((c)[2]), "+f"((c)[3])              \
        : "r"((a)[0]), "r"((a)[1]), "r"((a)[2]), "r"((a)[3]),                 \
          "r"(b0), "r"(b1))

__device__ __forceinline__ float gelu_f(float t) {
    return 0.5f * t * (1.0f + erff(t * 0.7071067811865475f));
}

// ---------------------------------------------------------------------------
// prep: block 0 folds latent into b1; blocks 1..64: L1 frags;
//       blocks 65..832: L2..L4 frags.  (fragment layout as round 7)
// ---------------------------------------------------------------------------
__global__ void prep_all_kernel(const float* __restrict__ emb,
                                const int* __restrict__ traj,
                                const float* __restrict__ W1,
                                const float* __restrict__ b1,
                                const float* __restrict__ W2,
                                const float* __restrict__ W3,
                                const float* __restrict__ W4) {
    int bid = blockIdx.x, tid = threadIdx.x;
    if (bid == 0) {
        int t = traj[0];
        const float* e = emb + (size_t)t * 128;
        float s = b1[tid];
#pragma unroll 4
        for (int k = 0; k < 128; ++k)
            s += e[k] * W1[(size_t)(25 + k) * HID + tid];
        g_b1p[tid] = s;
        return;
    }
    bool isL1 = (bid <= 64);
    int idx = isL1 ? (bid - 1) * 256 + tid : 0;
    int L = 0;
    if (!isL1) {
        int q = (bid - 65) * 256 + tid;
        L = q >> 16;
        idx = q & 65535;
    }
    int lane4 = idx & 3;
    int lane  = (idx >> 2) & 31;
    int g     = (idx >> 7) & 7;
    int warp  = (idx >> 10) & 7;
    int c     = isL1 ? 0 : ((idx >> 13) & 7);
    int half  = g >> 2;
    int ks    = (g >> 1) & 1;
    int npair = g & 1;
    int n8    = npair * 2 + (lane4 >> 1);
    int r     = lane4 & 1;
    int n = warp * 32 + n8 * 8 + (lane >> 2);
    int k = c * 32 + ks * 16 + (lane & 3) * 2 + r * 8;

    float w0, w1;
    if (isL1) {
        w0 = (k < 25)     ? W1[(size_t)k * HID + n]       : 0.0f;
        w1 = (k + 1 < 25) ? W1[(size_t)(k + 1) * HID + n] : 0.0f;
    } else {
        const float* W = (L == 0) ? W2 : ((L == 1) ? W3 : W4);
        w0 = W[(size_t)k * HID + n];
        w1 = W[(size_t)(k + 1) * HID + n];
    }
    __nv_bfloat16 h0 = __float2bfloat16_rn(w0);
    __nv_bfloat16 h1 = __float2bfloat16_rn(w1);
    uint32_t val;
    if (half == 0) {
        val = (uint32_t)*reinterpret_cast<uint16_t*>(&h0) |
              ((uint32_t)*reinterpret_cast<uint16_t*>(&h1) << 16);
    } else {
        __nv_bfloat16 l0 = __float2bfloat16_rn(w0 - __bfloat162float(h0));
        __nv_bfloat16 l1 = __float2bfloat16_rn(w1 - __bfloat162float(h1));
        val = (uint32_t)*reinterpret_cast<uint16_t*>(&l0) |
              ((uint32_t)*reinterpret_cast<uint16_t*>(&l1) << 16);
    }
    if (isL1) g_f1[idx] = val;
    else      g_fN[(size_t)L * 65536 + idx] = val;
}

// ---------------------------------------------------------------------------
// Fused kernel: one CTA per 64-row tile, 256 threads, warp tile 64M x 32N.
// ---------------------------------------------------------------------------
__global__ __launch_bounds__(256, 2)
void fused_kernel(const float* __restrict__ F, const float* __restrict__ C,
                  const float* __restrict__ b2, const float* __restrict__ b3,
                  const float* __restrict__ b4, const float* __restrict__ W5,
                  const float* __restrict__ b5, float* __restrict__ out) {
    extern __shared__ char smem[];
    const uint32_t sb = smem_u32(smem);
    const int tid = threadIdx.x, lane = tid & 31, warp = tid >> 5;
    const int tile = blockIdx.x;

    *reinterpret_cast<float*>(smem + BIAS_OFF + tid * 4) = g_b1p[tid];

    // --- in-kernel prep: invariants + polar rotation -> X0 into ACT, R -> RBUF
    if (tid < 64) {
        int p = tile * 64 + tid;
        float Fm[3][3];
#pragma unroll
        for (int i = 0; i < 3; ++i)
#pragma unroll
            for (int j = 0; j < 3; ++j)
                Fm[i][j] = F[(size_t)p * 9 + i * 3 + j];

        float G[3][3];
#pragma unroll
        for (int i = 0; i < 3; ++i)
#pragma unroll
            for (int j = 0; j < 3; ++j)
                G[i][j] = Fm[0][i] * Fm[0][j] + Fm[1][i] * Fm[1][j] + Fm[2][i] * Fm[2][j];

        float q = (G[0][0] + G[1][1] + G[2][2]) * (1.0f / 3.0f);
        float p1 = G[0][1] * G[0][1] + G[0][2] * G[0][2] + G[1][2] * G[1][2];
        float p2 = (G[0][0] - q) * (G[0][0] - q) + (G[1][1] - q) * (G[1][1] - q) +
                   (G[2][2] - q) * (G[2][2] - q) + 2.0f * p1;
        float e1, e2, e3;
        float pp = sqrtf(p2 * (1.0f / 6.0f));
        if (pp < 1e-20f) {
            e1 = e2 = e3 = q;
        } else {
            float ip = 1.0f / pp;
            float b00 = (G[0][0] - q) * ip, b11 = (G[1][1] - q) * ip, b22 = (G[2][2] - q) * ip;
            float b01 = G[0][1] * ip, b02 = G[0][2] * ip, b12 = G[1][2] * ip;
            float detB = b00 * (b11 * b22 - b12 * b12) - b01 * (b01 * b22 - b12 * b02) +
                         b02 * (b01 * b12 - b11 * b02);
            float r = fminf(1.0f, fmaxf(-1.0f, detB * 0.5f));
            float phi = acosf(r) * (1.0f / 3.0f);
            e1 = q + 2.0f * pp * cosf(phi);
            e3 = q + 2.0f * pp * cosf(phi + 2.0943951023931953f);
            e2 = 3.0f * q - e1 - e3;
        }
        float s1 = sqrtf(fmaxf(e1, 0.0f));
        float s2 = sqrtf(fmaxf(e2, 0.0f));
        float s3 = sqrtf(fmaxf(e3, 0.0f));

        float detF = Fm[0][0] * (Fm[1][1] * Fm[2][2] - Fm[1][2] * Fm[2][1]) -
                     Fm[0][1] * (Fm[1][0] * Fm[2][2] - Fm[1][2] * Fm[2][0]) +
                     Fm[0][2] * (Fm[1][0] * Fm[2][1] - Fm[1][1] * Fm[2][0]);

        float X[3][3];
#pragma unroll
        for (int i = 0; i < 3; ++i)
#pragma unroll
            for (int j = 0; j < 3; ++j) X[i][j] = Fm[i][j];
#pragma unroll
        for (int it = 0; it < 8; ++it) {
            float c00 = X[1][1] * X[2][2] - X[1][2] * X[2][1];
            float c01 = X[1][2] * X[2][0] - X[1][0] * X[2][2];
            float c02 = X[1][0] * X[2][1] - X[1][1] * X[2][0];
            float c10 = X[0][2] * X[2][1] - X[0][1] * X[2][2];
            float c11 = X[0][0] * X[2][2] - X[0][2] * X[2][0];
            float c12 = X[0][1] * X[2][0] - X[0][0] * X[2][1];
            float c20 = X[0][1] * X[1][2] - X[0][2] * X[1][1];
            float c21 = X[0][2] * X[1][0] - X[0][0] * X[1][2];
            float c22 = X[0][0] * X[1][1] - X[0][1] * X[1][0];
            float d = X[0][0] * c00 + X[0][1] * c01 + X[0][2] * c02;
            float id = 0.5f / d;
            X[0][0] = 0.5f * X[0][0] + id * c00;  X[0][1] = 0.5f * X[0][1] + id * c01;
            X[0][2] = 0.5f * X[0][2] + id * c02;  X[1][0] = 0.5f * X[1][0] + id * c10;
            X[1][1] = 0.5f * X[1][1] + id * c11;  X[1][2] = 0.5f * X[1][2] + id * c12;
            X[2][0] = 0.5f * X[2][0] + id * c20;  X[2][1] = 0.5f * X[2][1] + id * c21;
            X[2][2] = 0.5f * X[2][2] + id * c22;
        }
#pragma unroll
        for (int i = 0; i < 9; ++i)
            *reinterpret_cast<float*>(smem + RBUF + tid * 36 + i * 4) = X[i / 3][i % 3];

        float x0[32];
        x0[0] = s1 - 1.0f;  x0[1] = s2 - 1.0f;  x0[2] = s3 - 1.0f;
#pragma unroll
        for (int i = 0; i < 3; ++i)
#pragma unroll
            for (int j = 0; j < 3; ++j)
                x0[3 + i * 3 + j] = G[i][j] - ((i == j) ? 1.0f : 0.0f);
        x0[12] = detF - 1.0f;
        x0[13] = logf(detF) - 1.0f;
        float f00 = fmaxf(Fm[0][0], 1e-6f);
        x0[14] = f00 - 1.0f;
        x0[15] = logf(f00) - 1.0f;
#pragma unroll
        for (int k = 0; k < 9; ++k) x0[16 + k] = C[(size_t)p * 9 + k];
#pragma unroll
        for (int k = 25; k < 32; ++k) x0[k] = 0.0f;

#pragma unroll
        for (int cp = 0; cp < 16; ++cp) {
            float v0 = x0[2 * cp], v1 = x0[2 * cp + 1];
            __nv_bfloat162 h = __floats2bfloat162_rn(v0, v1);
            float l0 = v0 - __bfloat162float(__low2bfloat16(h));
            float l1 = v1 - __bfloat162float(__high2bfloat16(h));
            __nv_bfloat162 lo = __floats2bfloat162_rn(l0, l1);
            *reinterpret_cast<uint32_t*>(smem + ACT_H + tid * 528 + cp * 4) =
                *reinterpret_cast<uint32_t*>(&h);
            *reinterpret_cast<uint32_t*>(smem + ACT_L + tid * 528 + cp * 4) =
                *reinterpret_cast<uint32_t*>(&lo);
        }
    }
    __syncthreads();

    // --- mainloop: 25 chunks = L1(1) + L2..L4(8 each); no intra-layer syncs
    float acc[4][4][4];
#pragma unroll
    for (int mt = 0; mt < 4; ++mt)
#pragma unroll
        for (int n8 = 0; n8 < 4; ++n8)
#pragma unroll
            for (int r = 0; r < 4; ++r) acc[mt][n8][r] = 0.0f;

    const uint32_t a_off = (uint32_t)(lane & 15) * 528u + ((lane >> 4) << 4);

#pragma unroll 1
    for (int gi = 0; gi < 25; ++gi) {
        const int l  = (gi == 0) ? 0 : (((gi - 1) >> 3) + 1);
        const int ch = (gi == 0) ? 0 : ((gi - 1) & 7);
        const uint4* wbase = (l == 0)
            ? reinterpret_cast<const uint4*>(g_f1)
            : reinterpret_cast<const uint4*>(g_fN + (size_t)(l - 1) * 65536);
        const int fb = ((ch * 8 + warp) * 8) * 32 + lane;

        uint4 wfh[4], wfl[4];
#pragma unroll
        for (int g = 0; g < 4; ++g) {
            wfh[g] = __ldg(wbase + fb + g * 32);
            wfl[g] = __ldg(wbase + fb + (g + 4) * 32);
        }

        const uint32_t acol = (uint32_t)ch * 64u;
#pragma unroll
        for (int ks = 0; ks < 2; ++ks) {
            uint32_t bh[4][2], bl[4][2];
            {
                uint4 q0 = wfh[ks * 2], q1 = wfh[ks * 2 + 1];
                bh[0][0] = q0.x; bh[0][1] = q0.y; bh[1][0] = q0.z; bh[1][1] = q0.w;
                bh[2][0] = q1.x; bh[2][1] = q1.y; bh[3][0] = q1.z; bh[3][1] = q1.w;
                uint4 p0 = wfl[ks * 2], p1 = wfl[ks * 2 + 1];
                bl[0][0] = p0.x; bl[0][1] = p0.y; bl[1][0] = p0.z; bl[1][1] = p0.w;
                bl[2][0] = p1.x; bl[2][1] = p1.y; bl[3][0] = p1.z; bl[3][1] = p1.w;
            }
            // interleave per m-tile: 2 LDSM + 12 MMA, small live set
#pragma unroll
            for (int mt = 0; mt < 4; ++mt) {
                uint32_t ah[4], al[4];
                LDSM4(ah, sb + ACT_H + a_off + mt * 8448 + acol + ks * 32);
                LDSM4(al, sb + ACT_L + a_off + mt * 8448 + acol + ks * 32);
#pragma unroll
                for (int n8 = 0; n8 < 4; ++n8)
                    MMA_BF16(acc[mt][n8], ah, bh[n8][0], bh[n8][1]);
#pragma unroll
                for (int n8 = 0; n8 < 4; ++n8)
                    MMA_BF16(acc[mt][n8], al, bh[n8][0], bh[n8][1]);
#pragma unroll
                for (int n8 = 0; n8 < 4; ++n8)
                    MMA_BF16(acc[mt][n8], ah, bl[n8][0], bl[n8][1]);
            }
        }

        // --- layer boundary: GELU + split + write new act into SMEM --------
        const bool eol = (gi == 0) || (((gi - 1) & 7) == 7);
        if (eol) {
            __syncthreads();                   // all reads of old acts done
            const int r_l = lane >> 2, c_l = (lane & 3) << 1;
#pragma unroll
            for (int mt = 0; mt < 4; ++mt)
#pragma unroll
                for (int n8 = 0; n8 < 4; ++n8) {
                    int row = mt * 16 + r_l;
                    int col = warp * 32 + n8 * 8 + c_l;
                    float* a4 = acc[mt][n8];
                    float b0 = *reinterpret_cast<float*>(smem + BIAS_OFF + col * 4);
                    float b1v = *reinterpret_cast<float*>(smem + BIAS_OFF + (col + 1) * 4);
                    float g0 = gelu_f(a4[0] + b0);
                    float g1 = gelu_f(a4[1] + b1v);
                    float g2 = gelu_f(a4[2] + b0);
                    float g3 = gelu_f(a4[3] + b1v);
                    __nv_bfloat162 h01 = __floats2bfloat162_rn(g0, g1);
                    __nv_bfloat162 h23 = __floats2bfloat162_rn(g2, g3);
                    float l0 = g0 - __bfloat162float(__low2bfloat16(h01));
                    float l1 = g1 - __bfloat162float(__high2bfloat16(h01));
                    float l2 = g2 - __bfloat162float(__low2bfloat16(h23));
                    float l3 = g3 - __bfloat162float(__high2bfloat16(h23));
                    __nv_bfloat162 q01 = __floats2bfloat162_rn(l0, l1);
                    __nv_bfloat162 q23 = __floats2bfloat162_rn(l2, l3);
                    *reinterpret_cast<uint32_t*>(smem + ACT_H + row * 528 + col * 2) =
                        *reinterpret_cast<uint32_t*>(&h01);
                    *reinterpret_cast<uint32_t*>(smem + ACT_H + (row + 8) * 528 + col * 2) =
                        *reinterpret_cast<uint32_t*>(&h23);
                    *reinterpret_cast<uint32_t*>(smem + ACT_L + row * 528 + col * 2) =
                        *reinterpret_cast<uint32_t*>(&q01);
                    *reinterpret_cast<uint32_t*>(smem + ACT_L + (row + 8) * 528 + col * 2) =
                        *reinterpret_cast<uint32_t*>(&q23);
                    a4[0] = a4[1] = a4[2] = a4[3] = 0.0f;
                }
            if (l < 3) {
                const float* nb = (l == 0) ? b2 : ((l == 1) ? b3 : b4);
                *reinterpret_cast<float*>(smem + BIAS_OFF + tid * 4) = nb[tid];
            }
            __syncthreads();                   // new acts visible
        }
    }

    // --- final layer: 256 -> 9 + symmetrize + P=R@x, cauchy = P@F^T --------
    for (int i = tid; i < 2304; i += 256)
        *reinterpret_cast<float*>(smem + W5S + i * 4) = W5[i];
    if (tid < 9)
        *reinterpret_cast<float*>(smem + B5S + tid * 4) = b5[tid];
    __syncthreads();

#pragma unroll 1
    for (int rr = 0; rr < 8; ++rr) {
        int row = warp * 8 + rr;
        float s[9];
#pragma unroll
        for (int j = 0; j < 9; ++j) s[j] = 0.0f;
#pragma unroll
        for (int t4 = 0; t4 < 4; ++t4) {
            int cp = lane + 32 * t4;
            uint32_t hp = *reinterpret_cast<uint32_t*>(smem + ACT_H + row * 528 + cp * 4);
            uint32_t lp = *reinterpret_cast<uint32_t*>(smem + ACT_L + row * 528 + cp * 4);
            __nv_bfloat162 h = *reinterpret_cast<__nv_bfloat162*>(&hp);
            __nv_bfloat162 lo = *reinterpret_cast<__nv_bfloat162*>(&lp);
            float x0 = __bfloat162float(__low2bfloat16(h)) + __bfloat162float(__low2bfloat16(lo));
            float x1 = __bfloat162float(__high2bfloat16(h)) + __bfloat162float(__high2bfloat16(lo));
            const float* w0 = reinterpret_cast<const float*>(smem + W5S) + (2 * cp) * 9;
#pragma unroll
            for (int j = 0; j < 9; ++j) s[j] += x0 * w0[j] + x1 * w0[9 + j];
        }
#pragma unroll
        for (int j = 0; j < 9; ++j) {
#pragma unroll
            for (int o = 16; o >= 1; o >>= 1)
                s[j] += __shfl_xor_sync(0xffffffffu, s[j], o);
        }
        if (lane == 0) {
            int p = tile * 64 + row;
            float x[3][3], xs[3][3], Rm[3][3], Fm[3][3], P[3][3];
#pragma unroll
            for (int i = 0; i < 3; ++i)
#pragma unroll
                for (int j = 0; j < 3; ++j) {
                    x[i][j] = s[i * 3 + j] +
                              *reinterpret_cast<float*>(smem + B5S + (i * 3 + j) * 4);
                    Rm[i][j] = *reinterpret_cast<float*>(smem + RBUF + row * 36 + (i * 3 + j) * 4);
                    Fm[i][j] = F[(size_t)p * 9 + i * 3 + j];
                }
#pragma unroll
            for (int i = 0; i < 3; ++i)
#pragma unroll
                for (int j = 0; j < 3; ++j) xs[i][j] = 0.5f * (x[i][j] + x[j][i]);
#pragma unroll
            for (int i = 0; i < 3; ++i)
#pragma unroll
                for (int j = 0; j < 3; ++j)
                    P[i][j] = Rm[i][0] * xs[0][j] + Rm[i][1] * xs[1][j] + Rm[i][2] * xs[2][j];
#pragma unroll
            for (int i = 0; i < 3; ++i)
#pragma unroll
                for (int j = 0; j < 3; ++j)
                    out[(size_t)p * 9 + i * 3 + j] =
                        P[i][0] * Fm[j][0] + P[i][1] * Fm[j][1] + P[i][2] * Fm[j][2];
        }
    }
}

// ---------------------------------------------------------------------------
extern "C" void kernel_launch(void* const* d_in, const int* in_sizes, int n_in,
                              void* d_out, int out_size) {
    const float* F    = (const float*)d_in[0];
    const float* C    = (const float*)d_in[1];
    const float* emb  = (const float*)d_in[2];
    const int*   traj = (const int*)d_in[3];
    const float* W1   = (const float*)d_in[4];
    const float* b1   = (const float*)d_in[5];
    const float* W2   = (const float*)d_in[6];
    const float* b2   = (const float*)d_in[7];
    const float* W3   = (const float*)d_in[8];
    const float* b3   = (const float*)d_in[9];
    const float* W4   = (const float*)d_in[10];
    const float* b4   = (const float*)d_in[11];
    const float* W5   = (const float*)d_in[12];
    const float* b5   = (const float*)d_in[13];
    float* out = (float*)d_out;

    int B = in_sizes[0] / 9;
    if (B > MAXB) B = MAXB;

    static bool attr_set = false;
    if (!attr_set) {
        cudaFuncSetAttribute(fused_kernel,
                             cudaFuncAttributeMaxDynamicSharedMemorySize, SMEM_TOT);
        attr_set = true;
    }

    prep_all_kernel<<<833, 256>>>(emb, traj, W1, b1, W2, W3, W4);
    fused_kernel<<<B / 64, 256, SMEM_TOT>>>(F, C, b2, b3, b4, W5, b5, out);
}

// round 9
// speedup vs baseline: 3.3812x; 1.0569x over previous
#include <cuda_runtime.h>
#include <cuda_fp16.h>
#include <math.h>
#include <math_constants.h>
#include <stdint.h>

// ============================================================================
// StressNNEval — round 9: fp16 split precision (weights hi+lo fp16, acts fp16).
//   L1: 3-term on exact split X0 (1 chunk). L2..L4: 2-term (act-hi x (wh+wl)).
//   Acts stored hi/lo fp16 each layer; final layer reads hi+lo (no quant event).
//   Predicted rel_err ~5e-4 (3 act-quantization events x 2.8e-4, x1.37 calib).
//   mma units 75 -> 51 vs round 8.
// ============================================================================

#define MAXB 262144
#define HID  256

__device__ __align__(128) float    g_b1p[HID];
__device__ __align__(128) uint32_t g_f1[16384];        // L1 frags (hi+lo fp16)
__device__ __align__(128) uint32_t g_fN[3 * 65536];    // L2..L4 frags (hi+lo fp16)

// ---- smem layout (dynamic, 80192 B; 2 CTAs/SM) -----------------------------
#define ACT_H    0              // 64 rows x 528B (256 fp16 + pad)
#define ACT_L    33792
#define BIAS_OFF 67584          // 256 fp32
#define RBUF     68608          // 64 x 9 fp32
#define W5S      70912          // 256x9 fp32
#define B5S      80128
#define SMEM_TOT 80192

// ---------------------------------------------------------------------------
__device__ __forceinline__ uint32_t smem_u32(const void* p) {
    uint32_t a;
    asm("{ .reg .u64 t; cvta.to.shared.u64 t, %1; cvt.u32.u64 %0, t; }"
        : "=r"(a) : "l"(p));
    return a;
}
#define LDSM4(r, addr)                                                        \
    asm volatile("ldmatrix.sync.aligned.m8n8.x4.shared.b16 {%0,%1,%2,%3}, [%4];" \
        : "=r"((r)[0]), "=r"((r)[1]), "=r"((r)[2]), "=r"((r)[3]) : "r"(addr))

#define MMA_FP16(c, a, b0, b1)                                                \
    asm volatile("mma.sync.aligned.m16n8k16.row.col.f32.f16.f16.f32 "         \
        "{%0,%1,%2,%3}, {%4,%5,%6,%7}, {%8,%9}, {%0,%1,%2,%3};"               \
        : "+f"((c)[0]), "+f"((c)[1]), "+f"((c)[2]), "+f"((c)[3])              \
        : "r"((a)[0]), "r"((a)[1]), "r"((a)[2]), "r"((a)[3]),                 \
          "r"(b0), "r"(b1))

__device__ __forceinline__ float gelu_f(float t) {
    return 0.5f * t * (1.0f + erff(t * 0.7071067811865475f));
}

// ---------------------------------------------------------------------------
// prep: block 0 folds latent into b1; blocks 1..64: L1 frags;
//       blocks 65..832: L2..L4 frags.  (fragment layout as rounds 7/8,
//       values now fp16 hi / fp16 residual-lo)
// ---------------------------------------------------------------------------
__global__ void prep_all_kernel(const float* __restrict__ emb,
                                const int* __restrict__ traj,
                                const float* __restrict__ W1,
                                const float* __restrict__ b1,
                                const float* __restrict__ W2,
                                const float* __restrict__ W3,
                                const float* __restrict__ W4) {
    int bid = blockIdx.x, tid = threadIdx.x;
    if (bid == 0) {
        int t = traj[0];
        const float* e = emb + (size_t)t * 128;
        float s = b1[tid];
#pragma unroll 4
        for (int k = 0; k < 128; ++k)
            s += e[k] * W1[(size_t)(25 + k) * HID + tid];
        g_b1p[tid] = s;
        return;
    }
    bool isL1 = (bid <= 64);
    int idx = isL1 ? (bid - 1) * 256 + tid : 0;
    int L = 0;
    if (!isL1) {
        int q = (bid - 65) * 256 + tid;
        L = q >> 16;
        idx = q & 65535;
    }
    int lane4 = idx & 3;
    int lane  = (idx >> 2) & 31;
    int g     = (idx >> 7) & 7;
    int warp  = (idx >> 10) & 7;
    int c     = isL1 ? 0 : ((idx >> 13) & 7);
    int half  = g >> 2;
    int ks    = (g >> 1) & 1;
    int npair = g & 1;
    int n8    = npair * 2 + (lane4 >> 1);
    int r     = lane4 & 1;
    int n = warp * 32 + n8 * 8 + (lane >> 2);
    int k = c * 32 + ks * 16 + (lane & 3) * 2 + r * 8;

    float w0, w1;
    if (isL1) {
        w0 = (k < 25)     ? W1[(size_t)k * HID + n]       : 0.0f;
        w1 = (k + 1 < 25) ? W1[(size_t)(k + 1) * HID + n] : 0.0f;
    } else {
        const float* W = (L == 0) ? W2 : ((L == 1) ? W3 : W4);
        w0 = W[(size_t)k * HID + n];
        w1 = W[(size_t)(k + 1) * HID + n];
    }
    __half h0 = __float2half_rn(w0);
    __half h1 = __float2half_rn(w1);
    uint32_t val;
    if (half == 0) {
        val = (uint32_t)*reinterpret_cast<uint16_t*>(&h0) |
              ((uint32_t)*reinterpret_cast<uint16_t*>(&h1) << 16);
    } else {
        __half l0 = __float2half_rn(w0 - __half2float(h0));
        __half l1 = __float2half_rn(w1 - __half2float(h1));
        val = (uint32_t)*reinterpret_cast<uint16_t*>(&l0) |
              ((uint32_t)*reinterpret_cast<uint16_t*>(&l1) << 16);
    }
    if (isL1) g_f1[idx] = val;
    else      g_fN[(size_t)L * 65536 + idx] = val;
}

// ---------------------------------------------------------------------------
// Fused kernel: one CTA per 64-row tile, 256 threads, warp tile 64M x 32N.
// ---------------------------------------------------------------------------
__global__ __launch_bounds__(256, 2)
void fused_kernel(const float* __restrict__ F, const float* __restrict__ C,
                  const float* __restrict__ b2, const float* __restrict__ b3,
                  const float* __restrict__ b4, const float* __restrict__ W5,
                  const float* __restrict__ b5, float* __restrict__ out) {
    extern __shared__ char smem[];
    const uint32_t sb = smem_u32(smem);
    const int tid = threadIdx.x, lane = tid & 31, warp = tid >> 5;
    const int tile = blockIdx.x;

    *reinterpret_cast<float*>(smem + BIAS_OFF + tid * 4) = g_b1p[tid];

    // --- in-kernel prep: invariants + polar rotation -> X0 into ACT, R -> RBUF
    if (tid < 64) {
        int p = tile * 64 + tid;
        float Fm[3][3];
#pragma unroll
        for (int i = 0; i < 3; ++i)
#pragma unroll
            for (int j = 0; j < 3; ++j)
                Fm[i][j] = F[(size_t)p * 9 + i * 3 + j];

        float G[3][3];
#pragma unroll
        for (int i = 0; i < 3; ++i)
#pragma unroll
            for (int j = 0; j < 3; ++j)
                G[i][j] = Fm[0][i] * Fm[0][j] + Fm[1][i] * Fm[1][j] + Fm[2][i] * Fm[2][j];

        float q = (G[0][0] + G[1][1] + G[2][2]) * (1.0f / 3.0f);
        float p1 = G[0][1] * G[0][1] + G[0][2] * G[0][2] + G[1][2] * G[1][2];
        float p2 = (G[0][0] - q) * (G[0][0] - q) + (G[1][1] - q) * (G[1][1] - q) +
                   (G[2][2] - q) * (G[2][2] - q) + 2.0f * p1;
        float e1, e2, e3;
        float pp = sqrtf(p2 * (1.0f / 6.0f));
        if (pp < 1e-20f) {
            e1 = e2 = e3 = q;
        } else {
            float ip = 1.0f / pp;
            float b00 = (G[0][0] - q) * ip, b11 = (G[1][1] - q) * ip, b22 = (G[2][2] - q) * ip;
            float b01 = G[0][1] * ip, b02 = G[0][2] * ip, b12 = G[1][2] * ip;
            float detB = b00 * (b11 * b22 - b12 * b12) - b01 * (b01 * b22 - b12 * b02) +
                         b02 * (b01 * b12 - b11 * b02);
            float r = fminf(1.0f, fmaxf(-1.0f, detB * 0.5f));
            float phi = acosf(r) * (1.0f / 3.0f);
            e1 = q + 2.0f * pp * cosf(phi);
            e3 = q + 2.0f * pp * cosf(phi + 2.0943951023931953f);
            e2 = 3.0f * q - e1 - e3;
        }
        float s1 = sqrtf(fmaxf(e1, 0.0f));
        float s2 = sqrtf(fmaxf(e2, 0.0f));
        float s3 = sqrtf(fmaxf(e3, 0.0f));

        float detF = Fm[0][0] * (Fm[1][1] * Fm[2][2] - Fm[1][2] * Fm[2][1]) -
                     Fm[0][1] * (Fm[1][0] * Fm[2][2] - Fm[1][2] * Fm[2][0]) +
                     Fm[0][2] * (Fm[1][0] * Fm[2][1] - Fm[1][1] * Fm[2][0]);

        float X[3][3];
#pragma unroll
        for (int i = 0; i < 3; ++i)
#pragma unroll
            for (int j = 0; j < 3; ++j) X[i][j] = Fm[i][j];
#pragma unroll
        for (int it = 0; it < 8; ++it) {
            float c00 = X[1][1] * X[2][2] - X[1][2] * X[2][1];
            float c01 = X[1][2] * X[2][0] - X[1][0] * X[2][2];
            float c02 = X[1][0] * X[2][1] - X[1][1] * X[2][0];
            float c10 = X[0][2] * X[2][1] - X[0][1] * X[2][2];
            float c11 = X[0][0] * X[2][2] - X[0][2] * X[2][0];
            float c12 = X[0][1] * X[2][0] - X[0][0] * X[2][1];
            float c20 = X[0][1] * X[1][2] - X[0][2] * X[1][1];
            float c21 = X[0][2] * X[1][0] - X[0][0] * X[1][2];
            float c22 = X[0][0] * X[1][1] - X[0][1] * X[1][0];
            float d = X[0][0] * c00 + X[0][1] * c01 + X[0][2] * c02;
            float id = 0.5f / d;
            X[0][0] = 0.5f * X[0][0] + id * c00;  X[0][1] = 0.5f * X[0][1] + id * c01;
            X[0][2] = 0.5f * X[0][2] + id * c02;  X[1][0] = 0.5f * X[1][0] + id * c10;
            X[1][1] = 0.5f * X[1][1] + id * c11;  X[1][2] = 0.5f * X[1][2] + id * c12;
            X[2][0] = 0.5f * X[2][0] + id * c20;  X[2][1] = 0.5f * X[2][1] + id * c21;
            X[2][2] = 0.5f * X[2][2] + id * c22;
        }
#pragma unroll
        for (int i = 0; i < 9; ++i)
            *reinterpret_cast<float*>(smem + RBUF + tid * 36 + i * 4) = X[i / 3][i % 3];

        float x0[32];
        x0[0] = s1 - 1.0f;  x0[1] = s2 - 1.0f;  x0[2] = s3 - 1.0f;
#pragma unroll
        for (int i = 0; i < 3; ++i)
#pragma unroll
            for (int j = 0; j < 3; ++j)
                x0[3 + i * 3 + j] = G[i][j] - ((i == j) ? 1.0f : 0.0f);
        x0[12] = detF - 1.0f;
        x0[13] = logf(detF) - 1.0f;
        float f00 = fmaxf(Fm[0][0], 1e-6f);
        x0[14] = f00 - 1.0f;
        x0[15] = logf(f00) - 1.0f;
#pragma unroll
        for (int k = 0; k < 9; ++k) x0[16 + k] = C[(size_t)p * 9 + k];
#pragma unroll
        for (int k = 25; k < 32; ++k) x0[k] = 0.0f;

#pragma unroll
        for (int cp = 0; cp < 16; ++cp) {
            float v0 = x0[2 * cp], v1 = x0[2 * cp + 1];
            __half2 h = __floats2half2_rn(v0, v1);
            float l0 = v0 - __half2float(__low2half(h));
            float l1 = v1 - __half2float(__high2half(h));
            __half2 lo = __floats2half2_rn(l0, l1);
            *reinterpret_cast<uint32_t*>(smem + ACT_H + tid * 528 + cp * 4) =
                *reinterpret_cast<uint32_t*>(&h);
            *reinterpret_cast<uint32_t*>(smem + ACT_L + tid * 528 + cp * 4) =
                *reinterpret_cast<uint32_t*>(&lo);
        }
    }
    __syncthreads();

    // --- mainloop: 25 chunks = L1(1, 3-term) + L2..L4(8 each, 2-term) ------
    float acc[4][4][4];
#pragma unroll
    for (int mt = 0; mt < 4; ++mt)
#pragma unroll
        for (int n8 = 0; n8 < 4; ++n8)
#pragma unroll
            for (int r = 0; r < 4; ++r) acc[mt][n8][r] = 0.0f;

    const uint32_t a_off = (uint32_t)(lane & 15) * 528u + ((lane >> 4) << 4);

#pragma unroll 1
    for (int gi = 0; gi < 25; ++gi) {
        const int l  = (gi == 0) ? 0 : (((gi - 1) >> 3) + 1);
        const int ch = (gi == 0) ? 0 : ((gi - 1) & 7);
        const bool three = (gi == 0);
        const uint4* wbase = (l == 0)
            ? reinterpret_cast<const uint4*>(g_f1)
            : reinterpret_cast<const uint4*>(g_fN + (size_t)(l - 1) * 65536);
        const int fb = ((ch * 8 + warp) * 8) * 32 + lane;

        uint4 wfh[4], wfl[4];
#pragma unroll
        for (int g = 0; g < 4; ++g) {
            wfh[g] = __ldg(wbase + fb + g * 32);
            wfl[g] = __ldg(wbase + fb + (g + 4) * 32);
        }

        const uint32_t acol = (uint32_t)ch * 64u;
#pragma unroll
        for (int ks = 0; ks < 2; ++ks) {
            uint32_t bh[4][2], bl[4][2];
            {
                uint4 q0 = wfh[ks * 2], q1 = wfh[ks * 2 + 1];
                bh[0][0] = q0.x; bh[0][1] = q0.y; bh[1][0] = q0.z; bh[1][1] = q0.w;
                bh[2][0] = q1.x; bh[2][1] = q1.y; bh[3][0] = q1.z; bh[3][1] = q1.w;
                uint4 p0 = wfl[ks * 2], p1 = wfl[ks * 2 + 1];
                bl[0][0] = p0.x; bl[0][1] = p0.y; bl[1][0] = p0.z; bl[1][1] = p0.w;
                bl[2][0] = p1.x; bl[2][1] = p1.y; bl[3][0] = p1.z; bl[3][1] = p1.w;
            }
#pragma unroll
            for (int mt = 0; mt < 4; ++mt) {
                uint32_t ah[4];
                LDSM4(ah, sb + ACT_H + a_off + mt * 8448 + acol + ks * 32);
#pragma unroll
                for (int n8 = 0; n8 < 4; ++n8)
                    MMA_FP16(acc[mt][n8], ah, bh[n8][0], bh[n8][1]);
                if (three) {
                    uint32_t al[4];
                    LDSM4(al, sb + ACT_L + a_off + mt * 8448 + acol + ks * 32);
#pragma unroll
                    for (int n8 = 0; n8 < 4; ++n8)
                        MMA_FP16(acc[mt][n8], al, bh[n8][0], bh[n8][1]);
                }
#pragma unroll
                for (int n8 = 0; n8 < 4; ++n8)
                    MMA_FP16(acc[mt][n8], ah, bl[n8][0], bl[n8][1]);
            }
        }

        // --- layer boundary: GELU + split + write new act into SMEM --------
        const bool eol = (gi == 0) || (((gi - 1) & 7) == 7);
        if (eol) {
            __syncthreads();                   // all reads of old acts done
            const int r_l = lane >> 2, c_l = (lane & 3) << 1;
#pragma unroll
            for (int mt = 0; mt < 4; ++mt)
#pragma unroll
                for (int n8 = 0; n8 < 4; ++n8) {
                    int row = mt * 16 + r_l;
                    int col = warp * 32 + n8 * 8 + c_l;
                    float* a4 = acc[mt][n8];
                    float b0 = *reinterpret_cast<float*>(smem + BIAS_OFF + col * 4);
                    float b1v = *reinterpret_cast<float*>(smem + BIAS_OFF + (col + 1) * 4);
                    float g0 = gelu_f(a4[0] + b0);
                    float g1 = gelu_f(a4[1] + b1v);
                    float g2 = gelu_f(a4[2] + b0);
                    float g3 = gelu_f(a4[3] + b1v);
                    __half2 h01 = __floats2half2_rn(g0, g1);
                    __half2 h23 = __floats2half2_rn(g2, g3);
                    float l0 = g0 - __half2float(__low2half(h01));
                    float l1 = g1 - __half2float(__high2half(h01));
                    float l2 = g2 - __half2float(__low2half(h23));
                    float l3 = g3 - __half2float(__high2half(h23));
                    __half2 q01 = __floats2half2_rn(l0, l1);
                    __half2 q23 = __floats2half2_rn(l2, l3);
                    *reinterpret_cast<uint32_t*>(smem + ACT_H + row * 528 + col * 2) =
                        *reinterpret_cast<uint32_t*>(&h01);
                    *reinterpret_cast<uint32_t*>(smem + ACT_H + (row + 8) * 528 + col * 2) =
                        *reinterpret_cast<uint32_t*>(&h23);
                    *reinterpret_cast<uint32_t*>(smem + ACT_L + row * 528 + col * 2) =
                        *reinterpret_cast<uint32_t*>(&q01);
                    *reinterpret_cast<uint32_t*>(smem + ACT_L + (row + 8) * 528 + col * 2) =
                        *reinterpret_cast<uint32_t*>(&q23);
                    a4[0] = a4[1] = a4[2] = a4[3] = 0.0f;
                }
            if (l < 3) {
                const float* nb = (l == 0) ? b2 : ((l == 1) ? b3 : b4);
                *reinterpret_cast<float*>(smem + BIAS_OFF + tid * 4) = nb[tid];
            }
            __syncthreads();                   // new acts visible
        }
    }

    // --- final layer: 256 -> 9 (reads hi+lo) + symmetrize + R@x@F^T --------
    for (int i = tid; i < 2304; i += 256)
        *reinterpret_cast<float*>(smem + W5S + i * 4) = W5[i];
    if (tid < 9)
        *reinterpret_cast<float*>(smem + B5S + tid * 4) = b5[tid];
    __syncthreads();

#pragma unroll 1
    for (int rr = 0; rr < 8; ++rr) {
        int row = warp * 8 + rr;
        float s[9];
#pragma unroll
        for (int j = 0; j < 9; ++j) s[j] = 0.0f;
#pragma unroll
        for (int t4 = 0; t4 < 4; ++t4) {
            int cp = lane + 32 * t4;
            uint32_t hp = *reinterpret_cast<uint32_t*>(smem + ACT_H + row * 528 + cp * 4);
            uint32_t lp = *reinterpret_cast<uint32_t*>(smem + ACT_L + row * 528 + cp * 4);
            __half2 h = *reinterpret_cast<__half2*>(&hp);
            __half2 lo = *reinterpret_cast<__half2*>(&lp);
            float x0 = __half2float(__low2half(h)) + __half2float(__low2half(lo));
            float x1 = __half2float(__high2half(h)) + __half2float(__high2half(lo));
            const float* w0 = reinterpret_cast<const float*>(smem + W5S) + (2 * cp) * 9;
#pragma unroll
            for (int j = 0; j < 9; ++j) s[j] += x0 * w0[j] + x1 * w0[9 + j];
        }
#pragma unroll
        for (int j = 0; j < 9; ++j) {
#pragma unroll
            for (int o = 16; o >= 1; o >>= 1)
                s[j] += __shfl_xor_sync(0xffffffffu, s[j], o);
        }
        if (lane == 0) {
            int p = tile * 64 + row;
            float x[3][3], xs[3][3], Rm[3][3], Fm[3][3], P[3][3];
#pragma unroll
            for (int i = 0; i < 3; ++i)
#pragma unroll
                for (int j = 0; j < 3; ++j) {
                    x[i][j] = s[i * 3 + j] +
                              *reinterpret_cast<float*>(smem + B5S + (i * 3 + j) * 4);
                    Rm[i][j] = *reinterpret_cast<float*>(smem + RBUF + row * 36 + (i * 3 + j) * 4);
                    Fm[i][j] = F[(size_t)p * 9 + i * 3 + j];
                }
#pragma unroll
            for (int i = 0; i < 3; ++i)
#pragma unroll
                for (int j = 0; j < 3; ++j) xs[i][j] = 0.5f * (x[i][j] + x[j][i]);
#pragma unroll
            for (int i = 0; i < 3; ++i)
#pragma unroll
                for (int j = 0; j < 3; ++j)
                    P[i][j] = Rm[i][0] * xs[0][j] + Rm[i][1] * xs[1][j] + Rm[i][2] * xs[2][j];
#pragma unroll
            for (int i = 0; i < 3; ++i)
#pragma unroll
                for (int j = 0; j < 3; ++j)
                    out[(size_t)p * 9 + i * 3 + j] =
                        P[i][0] * Fm[j][0] + P[i][1] * Fm[j][1] + P[i][2] * Fm[j][2];
        }
    }
}

// ---------------------------------------------------------------------------
extern "C" void kernel_launch(void* const* d_in, const int* in_sizes, int n_in,
                              void* d_out, int out_size) {
    const float* F    = (const float*)d_in[0];
    const float* C    = (const float*)d_in[1];
    const float* emb  = (const float*)d_in[2];
    const int*   traj = (const int*)d_in[3];
    const float* W1   = (const float*)d_in[4];
    const float* b1   = (const float*)d_in[5];
    const float* W2   = (const float*)d_in[6];
    const float* b2   = (const float*)d_in[7];
    const float* W3   = (const float*)d_in[8];
    const float* b3   = (const float*)d_in[9];
    const float* W4   = (const float*)d_in[10];
    const float* b4   = (const float*)d_in[11];
    const float* W5   = (const float*)d_in[12];
    const float* b5   = (const float*)d_in[13];
    float* out = (float*)d_out;

    int B = in_sizes[0] / 9;
    if (B > MAXB) B = MAXB;

    static bool attr_set = false;
    if (!attr_set) {
        cudaFuncSetAttribute(fused_kernel,
                             cudaFuncAttributeMaxDynamicSharedMemorySize, SMEM_TOT);
        attr_set = true;
    }

    prep_all_kernel<<<833, 256>>>(emb, traj, W1, b1, W2, W3, W4);
    fused_kernel<<<B / 64, 256, SMEM_TOT>>>(F, C, b2, b3, b4, W5, b5, out);
}

// round 11
// speedup vs baseline: 3.4740x; 1.0274x over previous
#include <cuda_runtime.h>
#include <cuda_fp16.h>
#include <math.h>
#include <math_constants.h>
#include <stdint.h>

// ============================================================================
// StressNNEval — round 11: round-10 design with the smem-pointer bug fixed
// (C++ accesses use generic pointers; cvta'd integers only feed ldmatrix)
// and the bias race removed (all 4 biases staged upfront, read-only).
//   fp16 split; L1 3-term, L2..L4 2-term. Ping-pong hi-act buffers,
//   ONE barrier per interior boundary. Arithmetic identical to round 9.
// ============================================================================

#define MAXB 262144
#define HID  256

__device__ __align__(128) float    g_b1p[HID];
__device__ __align__(128) uint32_t g_f1[16384];        // L1 frags (hi+lo fp16)
__device__ __align__(128) uint32_t g_fN[3 * 65536];    // L2..L4 frags (hi+lo fp16)

// ---- smem layout (dynamic, 79168 B; 2 CTAs/SM) -----------------------------
#define ACT0     0              // 64 rows x 528B (hi acts, ping)
#define ACT1     33792          // 64 rows x 528B (hi acts, pong; L4 lo at end)
#define X0LO     67584          // 64 rows x 80B (X0 lo)        [dead after L1]
#define BIASALL  72704          // 4 x 256 fp32 (b1p,b2,b3,b4)  [dead after L4]
#define W5S      67584          // overlay: 256x9 fp32          [after mainloop]
#define RBUF     76800          // 64 x 9 fp32                  [persistent]
#define B5S      79104          // 9 fp32
#define SMEM_TOT 79168

// ---------------------------------------------------------------------------
__device__ __forceinline__ uint32_t smem_u32(const void* p) {
    uint32_t a;
    asm("{ .reg .u64 t; cvta.to.shared.u64 t, %1; cvt.u32.u64 %0, t; }"
        : "=r"(a) : "l"(p));
    return a;
}
#define LDSM4(r, addr)                                                        \
    asm volatile("ldmatrix.sync.aligned.m8n8.x4.shared.b16 {%0,%1,%2,%3}, [%4];" \
        : "=r"((r)[0]), "=r"((r)[1]), "=r"((r)[2]), "=r"((r)[3]) : "r"(addr))

#define MMA_FP16(c, a, b0, b1)                                                \
    asm volatile("mma.sync.aligned.m16n8k16.row.col.f32.f16.f16.f32 "         \
        "{%0,%1,%2,%3}, {%4,%5,%6,%7}, {%8,%9}, {%0,%1,%2,%3};"               \
        : "+f"((c)[0]), "+f"((c)[1]), "+f"((c)[2]), "+f"((c)[3])              \
        : "r"((a)[0]), "r"((a)[1]), "r"((a)[2]), "r"((a)[3]),                 \
          "r"(b0), "r"(b1))

__device__ __forceinline__ float gelu_f(float t) {
    return 0.5f * t * (1.0f + erff(t * 0.7071067811865475f));
}

// ---------------------------------------------------------------------------
// prep: block 0 folds latent into b1; blocks 1..64: L1 frags;
//       blocks 65..832: L2..L4 frags.  (fragment layout as rounds 7-9)
// ---------------------------------------------------------------------------
__global__ void prep_all_kernel(const float* __restrict__ emb,
                                const int* __restrict__ traj,
                                const float* __restrict__ W1,
                                const float* __restrict__ b1,
                                const float* __restrict__ W2,
                                const float* __restrict__ W3,
                                const float* __restrict__ W4) {
    int bid = blockIdx.x, tid = threadIdx.x;
    if (bid == 0) {
        int t = traj[0];
        const float* e = emb + (size_t)t * 128;
        float s = b1[tid];
#pragma unroll 4
        for (int k = 0; k < 128; ++k)
            s += e[k] * W1[(size_t)(25 + k) * HID + tid];
        g_b1p[tid] = s;
        return;
    }
    bool isL1 = (bid <= 64);
    int idx = isL1 ? (bid - 1) * 256 + tid : 0;
    int L = 0;
    if (!isL1) {
        int q = (bid - 65) * 256 + tid;
        L = q >> 16;
        idx = q & 65535;
    }
    int lane4 = idx & 3;
    int lane  = (idx >> 2) & 31;
    int g     = (idx >> 7) & 7;
    int warp  = (idx >> 10) & 7;
    int c     = isL1 ? 0 : ((idx >> 13) & 7);
    int half  = g >> 2;
    int ks    = (g >> 1) & 1;
    int npair = g & 1;
    int n8    = npair * 2 + (lane4 >> 1);
    int r     = lane4 & 1;
    int n = warp * 32 + n8 * 8 + (lane >> 2);
    int k = c * 32 + ks * 16 + (lane & 3) * 2 + r * 8;

    float w0, w1;
    if (isL1) {
        w0 = (k < 25)     ? W1[(size_t)k * HID + n]       : 0.0f;
        w1 = (k + 1 < 25) ? W1[(size_t)(k + 1) * HID + n] : 0.0f;
    } else {
        const float* W = (L == 0) ? W2 : ((L == 1) ? W3 : W4);
        w0 = W[(size_t)k * HID + n];
        w1 = W[(size_t)(k + 1) * HID + n];
    }
    __half h0 = __float2half_rn(w0);
    __half h1 = __float2half_rn(w1);
    uint32_t val;
    if (half == 0) {
        val = (uint32_t)*reinterpret_cast<uint16_t*>(&h0) |
              ((uint32_t)*reinterpret_cast<uint16_t*>(&h1) << 16);
    } else {
        __half l0 = __float2half_rn(w0 - __half2float(h0));
        __half l1 = __float2half_rn(w1 - __half2float(h1));
        val = (uint32_t)*reinterpret_cast<uint16_t*>(&l0) |
              ((uint32_t)*reinterpret_cast<uint16_t*>(&l1) << 16);
    }
    if (isL1) g_f1[idx] = val;
    else      g_fN[(size_t)L * 65536 + idx] = val;
}

// ---------------------------------------------------------------------------
// Fused kernel: one CTA per 64-row tile, 256 threads, warp tile 64M x 32N.
// ---------------------------------------------------------------------------
__global__ __launch_bounds__(256, 2)
void fused_kernel(const float* __restrict__ F, const float* __restrict__ C,
                  const float* __restrict__ b2, const float* __restrict__ b3,
                  const float* __restrict__ b4, const float* __restrict__ W5,
                  const float* __restrict__ b5, float* __restrict__ out) {
    extern __shared__ char smem[];
    const uint32_t sb = smem_u32(smem);
    const int tid = threadIdx.x, lane = tid & 31, warp = tid >> 5;
    const int tile = blockIdx.x;

    // stage ALL biases once (read-only afterwards; no races)
    {
        float* ba = reinterpret_cast<float*>(smem + BIASALL);
        ba[tid]       = g_b1p[tid];
        ba[256 + tid] = b2[tid];
        ba[512 + tid] = b3[tid];
        ba[768 + tid] = b4[tid];
    }

    // --- in-kernel prep: invariants + polar rotation -> X0 (hi->ACT0,
    //     lo->X0LO), R -> RBUF
    if (tid < 64) {
        int p = tile * 64 + tid;
        float Fm[3][3];
#pragma unroll
        for (int i = 0; i < 3; ++i)
#pragma unroll
            for (int j = 0; j < 3; ++j)
                Fm[i][j] = F[(size_t)p * 9 + i * 3 + j];

        float G[3][3];
#pragma unroll
        for (int i = 0; i < 3; ++i)
#pragma unroll
            for (int j = 0; j < 3; ++j)
                G[i][j] = Fm[0][i] * Fm[0][j] + Fm[1][i] * Fm[1][j] + Fm[2][i] * Fm[2][j];

        float q = (G[0][0] + G[1][1] + G[2][2]) * (1.0f / 3.0f);
        float p1 = G[0][1] * G[0][1] + G[0][2] * G[0][2] + G[1][2] * G[1][2];
        float p2 = (G[0][0] - q) * (G[0][0] - q) + (G[1][1] - q) * (G[1][1] - q) +
                   (G[2][2] - q) * (G[2][2] - q) + 2.0f * p1;
        float e1, e2, e3;
        float pp = sqrtf(p2 * (1.0f / 6.0f));
        if (pp < 1e-20f) {
            e1 = e2 = e3 = q;
        } else {
            float ip = 1.0f / pp;
            float b00 = (G[0][0] - q) * ip, b11 = (G[1][1] - q) * ip, b22 = (G[2][2] - q) * ip;
            float b01 = G[0][1] * ip, b02 = G[0][2] * ip, b12 = G[1][2] * ip;
            float detB = b00 * (b11 * b22 - b12 * b12) - b01 * (b01 * b22 - b12 * b02) +
                         b02 * (b01 * b12 - b11 * b02);
            float r = fminf(1.0f, fmaxf(-1.0f, detB * 0.5f));
            float phi = acosf(r) * (1.0f / 3.0f);
            e1 = q + 2.0f * pp * cosf(phi);
            e3 = q + 2.0f * pp * cosf(phi + 2.0943951023931953f);
            e2 = 3.0f * q - e1 - e3;
        }
        float s1 = sqrtf(fmaxf(e1, 0.0f));
        float s2 = sqrtf(fmaxf(e2, 0.0f));
        float s3 = sqrtf(fmaxf(e3, 0.0f));

        float detF = Fm[0][0] * (Fm[1][1] * Fm[2][2] - Fm[1][2] * Fm[2][1]) -
                     Fm[0][1] * (Fm[1][0] * Fm[2][2] - Fm[1][2] * Fm[2][0]) +
                     Fm[0][2] * (Fm[1][0] * Fm[2][1] - Fm[1][1] * Fm[2][0]);

        float X[3][3];
#pragma unroll
        for (int i = 0; i < 3; ++i)
#pragma unroll
            for (int j = 0; j < 3; ++j) X[i][j] = Fm[i][j];
#pragma unroll
        for (int it = 0; it < 8; ++it) {
            float c00 = X[1][1] * X[2][2] - X[1][2] * X[2][1];
            float c01 = X[1][2] * X[2][0] - X[1][0] * X[2][2];
            float c02 = X[1][0] * X[2][1] - X[1][1] * X[2][0];
            float c10 = X[0][2] * X[2][1] - X[0][1] * X[2][2];
            float c11 = X[0][0] * X[2][2] - X[0][2] * X[2][0];
            float c12 = X[0][1] * X[2][0] - X[0][0] * X[2][1];
            float c20 = X[0][1] * X[1][2] - X[0][2] * X[1][1];
            float c21 = X[0][2] * X[1][0] - X[0][0] * X[1][2];
            float c22 = X[0][0] * X[1][1] - X[0][1] * X[1][0];
            float d = X[0][0] * c00 + X[0][1] * c01 + X[0][2] * c02;
            float id = 0.5f / d;
            X[0][0] = 0.5f * X[0][0] + id * c00;  X[0][1] = 0.5f * X[0][1] + id * c01;
            X[0][2] = 0.5f * X[0][2] + id * c02;  X[1][0] = 0.5f * X[1][0] + id * c10;
            X[1][1] = 0.5f * X[1][1] + id * c11;  X[1][2] = 0.5f * X[1][2] + id * c12;
            X[2][0] = 0.5f * X[2][0] + id * c20;  X[2][1] = 0.5f * X[2][1] + id * c21;
            X[2][2] = 0.5f * X[2][2] + id * c22;
        }
#pragma unroll
        for (int i = 0; i < 9; ++i)
            reinterpret_cast<float*>(smem + RBUF)[tid * 9 + i] = X[i / 3][i % 3];

        float x0[32];
        x0[0] = s1 - 1.0f;  x0[1] = s2 - 1.0f;  x0[2] = s3 - 1.0f;
#pragma unroll
        for (int i = 0; i < 3; ++i)
#pragma unroll
            for (int j = 0; j < 3; ++j)
                x0[3 + i * 3 + j] = G[i][j] - ((i == j) ? 1.0f : 0.0f);
        x0[12] = detF - 1.0f;
        x0[13] = logf(detF) - 1.0f;
        float f00 = fmaxf(Fm[0][0], 1e-6f);
        x0[14] = f00 - 1.0f;
        x0[15] = logf(f00) - 1.0f;
#pragma unroll
        for (int k = 0; k < 9; ++k) x0[16 + k] = C[(size_t)p * 9 + k];
#pragma unroll
        for (int k = 25; k < 32; ++k) x0[k] = 0.0f;

#pragma unroll
        for (int cp = 0; cp < 16; ++cp) {
            float v0 = x0[2 * cp], v1 = x0[2 * cp + 1];
            __half2 h = __floats2half2_rn(v0, v1);
            float l0 = v0 - __half2float(__low2half(h));
            float l1 = v1 - __half2float(__high2half(h));
            __half2 lo = __floats2half2_rn(l0, l1);
            *reinterpret_cast<uint32_t*>(smem + ACT0 + tid * 528 + cp * 4) =
                *reinterpret_cast<uint32_t*>(&h);
            *reinterpret_cast<uint32_t*>(smem + X0LO + tid * 80 + cp * 4) =
                *reinterpret_cast<uint32_t*>(&lo);
        }
    }
    __syncthreads();

    // --- mainloop over layers; chunks inside; ping-pong act buffers --------
    float acc[4][4][4];
#pragma unroll
    for (int mt = 0; mt < 4; ++mt)
#pragma unroll
        for (int n8 = 0; n8 < 4; ++n8)
#pragma unroll
            for (int r = 0; r < 4; ++r) acc[mt][n8][r] = 0.0f;

    const uint32_t a_off    = (uint32_t)(lane & 15) * 528u + ((lane >> 4) << 4);
    const uint32_t a_off_lo = (uint32_t)(lane & 15) * 80u  + ((lane >> 4) << 4);
    const int r_l = lane >> 2, c_l = (lane & 3) << 1;

#pragma unroll 1
    for (int l = 0; l < 4; ++l) {
        const int nch = (l == 0) ? 1 : 8;
        const uint32_t rd = sb + ((l & 1) ? ACT1 : ACT0);   // LDSM only
        const uint4* wbase = (l == 0)
            ? reinterpret_cast<const uint4*>(g_f1)
            : reinterpret_cast<const uint4*>(g_fN + (size_t)(l - 1) * 65536);
        const float* bias = reinterpret_cast<const float*>(smem + BIASALL) + l * 256;

#pragma unroll 1
        for (int ch = 0; ch < nch; ++ch) {
            const int fb = ((ch * 8 + warp) * 8) * 32 + lane;
            uint4 wfh[4], wfl[4];
#pragma unroll
            for (int g = 0; g < 4; ++g) {
                wfh[g] = __ldg(wbase + fb + g * 32);
                wfl[g] = __ldg(wbase + fb + (g + 4) * 32);
            }
            const uint32_t acol = (uint32_t)ch * 64u;
#pragma unroll
            for (int ks = 0; ks < 2; ++ks) {
                uint32_t bh[4][2], bl[4][2];
                {
                    uint4 q0 = wfh[ks * 2], q1 = wfh[ks * 2 + 1];
                    bh[0][0] = q0.x; bh[0][1] = q0.y; bh[1][0] = q0.z; bh[1][1] = q0.w;
                    bh[2][0] = q1.x; bh[2][1] = q1.y; bh[3][0] = q1.z; bh[3][1] = q1.w;
                    uint4 p0 = wfl[ks * 2], p1 = wfl[ks * 2 + 1];
                    bl[0][0] = p0.x; bl[0][1] = p0.y; bl[1][0] = p0.z; bl[1][1] = p0.w;
                    bl[2][0] = p1.x; bl[2][1] = p1.y; bl[3][0] = p1.z; bl[3][1] = p1.w;
                }
#pragma unroll
                for (int mt = 0; mt < 4; ++mt) {
                    uint32_t ah[4];
                    LDSM4(ah, rd + a_off + mt * 8448 + acol + ks * 32);
#pragma unroll
                    for (int n8 = 0; n8 < 4; ++n8)
                        MMA_FP16(acc[mt][n8], ah, bh[n8][0], bh[n8][1]);
                    if (l == 0) {
                        uint32_t al[4];
                        LDSM4(al, sb + X0LO + a_off_lo + mt * 1280 + ks * 32);
#pragma unroll
                        for (int n8 = 0; n8 < 4; ++n8)
                            MMA_FP16(acc[mt][n8], al, bh[n8][0], bh[n8][1]);
                    }
#pragma unroll
                    for (int n8 = 0; n8 < 4; ++n8)
                        MMA_FP16(acc[mt][n8], ah, bl[n8][0], bl[n8][1]);
                }
            }
        }

        // --- layer boundary ------------------------------------------------
        if (l < 3) {
            // hi-only epilogue into the OTHER buffer; one barrier
            char* wr = smem + ((l & 1) ? ACT0 : ACT1);
#pragma unroll
            for (int mt = 0; mt < 4; ++mt)
#pragma unroll
                for (int n8 = 0; n8 < 4; ++n8) {
                    int row = mt * 16 + r_l;
                    int col = warp * 32 + n8 * 8 + c_l;
                    float* a4 = acc[mt][n8];
                    float b0 = bias[col];
                    float b1v = bias[col + 1];
                    float g0 = gelu_f(a4[0] + b0);
                    float g1 = gelu_f(a4[1] + b1v);
                    float g2 = gelu_f(a4[2] + b0);
                    float g3 = gelu_f(a4[3] + b1v);
                    __half2 h01 = __floats2half2_rn(g0, g1);
                    __half2 h23 = __floats2half2_rn(g2, g3);
                    *reinterpret_cast<uint32_t*>(wr + row * 528 + col * 2) =
                        *reinterpret_cast<uint32_t*>(&h01);
                    *reinterpret_cast<uint32_t*>(wr + (row + 8) * 528 + col * 2) =
                        *reinterpret_cast<uint32_t*>(&h23);
                    a4[0] = a4[1] = a4[2] = a4[3] = 0.0f;
                }
            __syncthreads();
        } else {
            // L4: pass 1 — gelu (stash g in acc), hi -> ACT0 (dead L2 acts)
#pragma unroll
            for (int mt = 0; mt < 4; ++mt)
#pragma unroll
                for (int n8 = 0; n8 < 4; ++n8) {
                    int row = mt * 16 + r_l;
                    int col = warp * 32 + n8 * 8 + c_l;
                    float* a4 = acc[mt][n8];
                    float b0 = bias[col];
                    float b1v = bias[col + 1];
                    a4[0] = gelu_f(a4[0] + b0);
                    a4[1] = gelu_f(a4[1] + b1v);
                    a4[2] = gelu_f(a4[2] + b0);
                    a4[3] = gelu_f(a4[3] + b1v);
                    __half2 h01 = __floats2half2_rn(a4[0], a4[1]);
                    __half2 h23 = __floats2half2_rn(a4[2], a4[3]);
                    *reinterpret_cast<uint32_t*>(smem + ACT0 + row * 528 + col * 2) =
                        *reinterpret_cast<uint32_t*>(&h01);
                    *reinterpret_cast<uint32_t*>(smem + ACT0 + (row + 8) * 528 + col * 2) =
                        *reinterpret_cast<uint32_t*>(&h23);
                }
            __syncthreads();   // all L4 mma reads of ACT1 complete
            // pass 2 — lo = g - hi -> ACT1
#pragma unroll
            for (int mt = 0; mt < 4; ++mt)
#pragma unroll
                for (int n8 = 0; n8 < 4; ++n8) {
                    int row = mt * 16 + r_l;
                    int col = warp * 32 + n8 * 8 + c_l;
                    float* a4 = acc[mt][n8];
                    __half2 h01 = __floats2half2_rn(a4[0], a4[1]);
                    __half2 h23 = __floats2half2_rn(a4[2], a4[3]);
                    float l0 = a4[0] - __half2float(__low2half(h01));
                    float l1 = a4[1] - __half2float(__high2half(h01));
                    float l2 = a4[2] - __half2float(__low2half(h23));
                    float l3 = a4[3] - __half2float(__high2half(h23));
                    __half2 q01 = __floats2half2_rn(l0, l1);
                    __half2 q23 = __floats2half2_rn(l2, l3);
                    *reinterpret_cast<uint32_t*>(smem + ACT1 + row * 528 + col * 2) =
                        *reinterpret_cast<uint32_t*>(&q01);
                    *reinterpret_cast<uint32_t*>(smem + ACT1 + (row + 8) * 528 + col * 2) =
                        *reinterpret_cast<uint32_t*>(&q23);
                }
        }
    }

    // --- final layer: 256 -> 9 (hi from ACT0, lo from ACT1) ----------------
    __syncthreads();           // lo writes visible; X0LO/BIASALL now dead
    for (int i = tid; i < 2304; i += 256)
        reinterpret_cast<float*>(smem + W5S)[i] = W5[i];
    if (tid < 9)
        reinterpret_cast<float*>(smem + B5S)[tid] = b5[tid];
    __syncthreads();

#pragma unroll 1
    for (int rr = 0; rr < 8; ++rr) {
        int row = warp * 8 + rr;
        float s[9];
#pragma unroll
        for (int j = 0; j < 9; ++j) s[j] = 0.0f;
#pragma unroll
        for (int t4 = 0; t4 < 4; ++t4) {
            int cp = lane + 32 * t4;
            uint32_t hp = *reinterpret_cast<uint32_t*>(smem + ACT0 + row * 528 + cp * 4);
            uint32_t lp = *reinterpret_cast<uint32_t*>(smem + ACT1 + row * 528 + cp * 4);
            __half2 h = *reinterpret_cast<__half2*>(&hp);
            __half2 lo = *reinterpret_cast<__half2*>(&lp);
            float x0 = __half2float(__low2half(h)) + __half2float(__low2half(lo));
            float x1 = __half2float(__high2half(h)) + __half2float(__high2half(lo));
            const float* w0 = reinterpret_cast<const float*>(smem + W5S) + (2 * cp) * 9;
#pragma unroll
            for (int j = 0; j < 9; ++j) s[j] += x0 * w0[j] + x1 * w0[9 + j];
        }
#pragma unroll
        for (int j = 0; j < 9; ++j) {
#pragma unroll
            for (int o = 16; o >= 1; o >>= 1)
                s[j] += __shfl_xor_sync(0xffffffffu, s[j], o);
        }
        if (lane == 0) {
            int p = tile * 64 + row;
            float x[3][3], xs[3][3], Rm[3][3], Fm[3][3], P[3][3];
#pragma unroll
            for (int i = 0; i < 3; ++i)
#pragma unroll
                for (int j = 0; j < 3; ++j) {
                    x[i][j] = s[i * 3 + j] +
                              reinterpret_cast<float*>(smem + B5S)[i * 3 + j];
                    Rm[i][j] = reinterpret_cast<float*>(smem + RBUF)[row * 9 + i * 3 + j];
                    Fm[i][j] = F[(size_t)p * 9 + i * 3 + j];
                }
#pragma unroll
            for (int i = 0; i < 3; ++i)
#pragma unroll
                for (int j = 0; j < 3; ++j) xs[i][j] = 0.5f * (x[i][j] + x[j][i]);
#pragma unroll
            for (int i = 0; i < 3; ++i)
#pragma unroll
                for (int j = 0; j < 3; ++j)
                    P[i][j] = Rm[i][0] * xs[0][j] + Rm[i][1] * xs[1][j] + Rm[i][2] * xs[2][j];
#pragma unroll
            for (int i = 0; i < 3; ++i)
#pragma unroll
                for (int j = 0; j < 3; ++j)
                    out[(size_t)p * 9 + i * 3 + j] =
                        P[i][0] * Fm[j][0] + P[i][1] * Fm[j][1] + P[i][2] * Fm[j][2];
        }
    }
}

// ---------------------------------------------------------------------------
extern "C" void kernel_launch(void* const* d_in, const int* in_sizes, int n_in,
                              void* d_out, int out_size) {
    const float* F    = (const float*)d_in[0];
    const float* C    = (const float*)d_in[1];
    const float* emb  = (const float*)d_in[2];
    const int*   traj = (const int*)d_in[3];
    const float* W1   = (const float*)d_in[4];
    const float* b1   = (const float*)d_in[5];
    const float* W2   = (const float*)d_in[6];
    const float* b2   = (const float*)d_in[7];
    const float* W3   = (const float*)d_in[8];
    const float* b3   = (const float*)d_in[9];
    const float* W4   = (const float*)d_in[10];
    const float* b4   = (const float*)d_in[11];
    const float* W5   = (const float*)d_in[12];
    const float* b5   = (const float*)d_in[13];
    float* out = (float*)d_out;

    int B = in_sizes[0] / 9;
    if (B > MAXB) B = MAXB;

    static bool attr_set = false;
    if (!attr_set) {
        cudaFuncSetAttribute(fused_kernel,
                             cudaFuncAttributeMaxDynamicSharedMemorySize, SMEM_TOT);
        attr_set = true;
    }

    prep_all_kernel<<<833, 256>>>(emb, traj, W1, b1, W2, W3, W4);
    fused_kernel<<<B / 64, 256, SMEM_TOT>>>(F, C, b2, b3, b4, W5, b5, out);
}